// round 1
// baseline (speedup 1.0000x reference)
#include <cuda_runtime.h>

constexpr int T_ = 64, B_ = 64, N_ = 64, D_ = 128, HID_ = 256;
constexpr int BND = B_ * N_ * D_;                      // 524288
constexpr size_t TOT  = (size_t)T_ * BND;              // 33554432
constexpr size_t TOTH = (size_t)T_ * B_ * N_ * HID_;   // 67108864

// -------- scratch (no allocations allowed) --------
__device__ float g_M[64 * 64];
__device__ float g_mlp[TOT];
__device__ float g_q[TOT];
__device__ float g_k[TOT];
__device__ float g_v[TOT];
__device__ float g_o[TOT];
__device__ float g_xg[TOT];
__device__ float g_h1[TOTH];

// =====================================================================
// Kernel 0: build the DCT lowpass operator M = C[:16]^T C[:16]  (64x64)
// C[k,t] = cos(pi*(t+0.5)*k/64)*sqrt(2/64), row 0 scaled by 1/sqrt(2).
// Mean-subtract + re-add in the reference cancels exactly against k=0.
// =====================================================================
__global__ void k_dct() {
    int t = blockIdx.x, s = threadIdx.x;
    const double PI = 3.141592653589793238462643383279502884;
    double acc = 0.0;
    for (int kk = 0; kk < 16; kk++) {
        double scale = (kk == 0) ? sqrt(1.0 / 64.0) : sqrt(2.0 / 64.0);
        float ct = (float)(cos(PI * (t + 0.5) * kk / 64.0) * scale);
        float cs = (float)(cos(PI * (s + 0.5) * kk / 64.0) * scale);
        acc += (double)ct * (double)cs;
    }
    g_M[t * 64 + s] = (float)acc;
}

// =====================================================================
// Kernel 1: memory mix + temporal lowpass.
// Per block (b,n): mxp[s,d] = x[s,b,n,d] * (0.05*mx + 0.95*mx)[n,b,s,d]
// then mlp[t,b,n,d] = sum_s M[t,s] * mxp[s,d].
// =====================================================================
__global__ void __launch_bounds__(128) k_mix(const float* __restrict__ x,
                                             const float* __restrict__ mx) {
    __shared__ float s_p[64 * 128];   // 32 KB
    __shared__ float s_M[64 * 64];    // 16 KB
    const int bn = blockIdx.x;
    const int b = bn >> 6, n = bn & 63;
    const int tid = threadIdx.x;

    for (int i = tid; i < 4096; i += 128) s_M[i] = g_M[i];

    const float* xb = x + (size_t)(b * N_ + n) * D_;
    const float* mb = mx + ((size_t)(n * B_ + b) * T_) * D_;
    for (int i = tid; i < 8192; i += 128) {
        int s = i >> 7, d = i & 127;
        float mv = mb[i];
        // forward of 0.05*mx + 0.95*stop_grad(mx), fast-math-proof
        float mv2 = __fadd_rn(__fmul_rn(0.05f, mv), __fmul_rn(0.95f, mv));
        s_p[i] = __fmul_rn(xb[(size_t)s * BND + d], mv2);
        (void)s;
    }
    __syncthreads();

    const int d = tid;
    float col[64];
#pragma unroll
    for (int s = 0; s < 64; s++) col[s] = s_p[s * 128 + d];

    float* ob = g_mlp + (size_t)(b * N_ + n) * D_ + d;
    for (int t = 0; t < 64; t++) {
        float acc = 0.f;
#pragma unroll
        for (int s = 0; s < 64; s++) acc += s_M[t * 64 + s] * col[s];
        ob[(size_t)t * BND] = acc;
    }
}

// =====================================================================
// GEMM (64 t-rows x 128 out-cols per (b,n) block) + fused LIF scan.
// MODE 0: write spike {0,1} to out.
// MODE 1: write gx * (1 - spike) to out (gating epilogue).
// =====================================================================
template <int DIN, int MODE>
__global__ void __launch_bounds__(256) k_gemm_lif(
    const float* __restrict__ in, const float* __restrict__ W, int ldw, int wcol0,
    float* __restrict__ out, int ldo, int ocol0, const float* __restrict__ gx) {
    constexpr int SIN_LD = DIN + 1;  // pad to kill bank conflicts on a-loads
    extern __shared__ float sm[];
    float* s_in  = sm;                  // 64 * SIN_LD
    float* s_W   = sm + 64 * SIN_LD;    // DIN * 128
    float* s_pre = s_W + DIN * 128;     // 64 * 128
    const int bn = blockIdx.x;
    const int b = bn >> 6, n = bn & 63;
    const int tid = threadIdx.x;

    for (int i = tid; i < DIN * 128; i += 256) {
        int r = i >> 7, c = i & 127;
        s_W[i] = W[(size_t)r * ldw + wcol0 + c];
    }
    const size_t istride = (size_t)B_ * N_ * DIN;
    const float* ib = in + (size_t)(b * N_ + n) * DIN;
    for (int i = tid; i < 64 * DIN; i += 256) {
        int t = i / DIN, d = i % DIN;
        s_in[t * SIN_LD + d] = ib[(size_t)t * istride + d];
    }
    __syncthreads();

    const int c0 = (tid & 15) << 3;
    const int t0 = (tid >> 4) << 2;
    float acc[4][8];
#pragma unroll
    for (int i = 0; i < 4; i++)
#pragma unroll
        for (int j = 0; j < 8; j++) acc[i][j] = 0.f;

#pragma unroll 4
    for (int r = 0; r < DIN; r++) {
        float a0 = s_in[(t0 + 0) * SIN_LD + r];
        float a1 = s_in[(t0 + 1) * SIN_LD + r];
        float a2 = s_in[(t0 + 2) * SIN_LD + r];
        float a3 = s_in[(t0 + 3) * SIN_LD + r];
        float4 bv0 = *reinterpret_cast<const float4*>(&s_W[r * 128 + c0]);
        float4 bv1 = *reinterpret_cast<const float4*>(&s_W[r * 128 + c0 + 4]);
        float bb[8] = {bv0.x, bv0.y, bv0.z, bv0.w, bv1.x, bv1.y, bv1.z, bv1.w};
#pragma unroll
        for (int j = 0; j < 8; j++) {
            acc[0][j] += a0 * bb[j];
            acc[1][j] += a1 * bb[j];
            acc[2][j] += a2 * bb[j];
            acc[3][j] += a3 * bb[j];
        }
    }
#pragma unroll
    for (int i = 0; i < 4; i++)
#pragma unroll
        for (int j = 0; j < 8; j++) s_pre[(t0 + i) * 128 + c0 + j] = acc[i][j];
    __syncthreads();

    // LIF scan over time: v=0; v += (p-v)/2; spike at v>=1; hard reset.
    if (tid < 128) {
        const int c = tid;
        float vmem = 0.f;
        const size_t obase = (size_t)(b * N_ + n) * ldo + ocol0 + c;
        const size_t ostride = (size_t)B_ * N_ * ldo;
        const size_t gbase = (size_t)(b * N_ + n) * D_ + c;  // MODE 1: ldo==D_, ocol0==0
#pragma unroll 1
        for (int t = 0; t < 64; t++) {
            float p = s_pre[t * 128 + c];
            vmem = __fadd_rn(vmem, __fmul_rn(__fsub_rn(p, vmem), 0.5f));
            float spk = (vmem >= 1.0f) ? 1.0f : 0.0f;
            if (vmem >= 1.0f) vmem = 0.0f;
            size_t oi = obase + (size_t)t * ostride;
            if (MODE == 0) {
                out[oi] = spk;
            } else {
                float g = gx[gbase + (size_t)t * (size_t)BND];
                out[oi] = __fmul_rn(g, __fsub_rn(1.0f, spk));
            }
        }
    }
}

// =====================================================================
// Attention per (t,b): attn[h,n,m] = 0.125 * <q[n,head h], k[m,head h]>,
// o[n,d] = sum_m attn[h(d),n,m] * v[m,d].  All values exact in fp32.
// =====================================================================
__global__ void __launch_bounds__(256) k_attn(const float* __restrict__ q,
                                              const float* __restrict__ k,
                                              const float* __restrict__ v,
                                              float* __restrict__ o) {
    extern __shared__ float sm[];
    float* s_qT = sm;                 // [128 d][65] (padded)
    float* s_kT = s_qT + 128 * 65;    // [128 d][65]
    float* s_v  = s_kT + 128 * 65;    // [64 m][128 d]
    float* s_a  = s_v + 64 * 128;     // [2*64 n][65] (padded)
    const int tb = blockIdx.x;
    const size_t base = (size_t)tb * 8192;
    const int tid = threadIdx.x;

    for (int i = tid; i < 8192; i += 256) {
        int nn = i >> 7, dd = i & 127;
        float qv = q[base + i];
        float kv = k[base + i];
        s_qT[dd * 65 + nn] = qv;
        s_kT[dd * 65 + nn] = kv;
        s_v[i] = v[base + i];
    }
    __syncthreads();

    {   // attn phase: 2 heads, per thread 4n x 8m
        const int h = tid >> 7;
        const int r = tid & 127;
        const int n0 = (r >> 3) << 2;
        const int m0 = (r & 7) << 3;
        const int db = h << 6;
        float acc[4][8];
#pragma unroll
        for (int i = 0; i < 4; i++)
#pragma unroll
            for (int j = 0; j < 8; j++) acc[i][j] = 0.f;
        for (int d2 = 0; d2 < 64; d2++) {
            const float* qrow = &s_qT[(db + d2) * 65];
            const float* krow = &s_kT[(db + d2) * 65 + m0];
            float a0 = qrow[n0], a1 = qrow[n0 + 1], a2 = qrow[n0 + 2], a3 = qrow[n0 + 3];
            float bb[8];
#pragma unroll
            for (int j = 0; j < 8; j++) bb[j] = krow[j];
#pragma unroll
            for (int j = 0; j < 8; j++) {
                acc[0][j] += a0 * bb[j];
                acc[1][j] += a1 * bb[j];
                acc[2][j] += a2 * bb[j];
                acc[3][j] += a3 * bb[j];
            }
        }
#pragma unroll
        for (int i = 0; i < 4; i++)
#pragma unroll
            for (int j = 0; j < 8; j++)
                s_a[(h * 64 + n0 + i) * 65 + m0 + j] = acc[i][j] * 0.125f;
    }
    __syncthreads();

    {   // o phase: per thread 4n x 8d
        const int n0 = (tid >> 4) << 2;
        const int d0 = (tid & 15) << 3;
        const int h = d0 >> 6;
        float acc[4][8];
#pragma unroll
        for (int i = 0; i < 4; i++)
#pragma unroll
            for (int j = 0; j < 8; j++) acc[i][j] = 0.f;
        for (int m = 0; m < 64; m++) {
            float4 bv0 = *reinterpret_cast<const float4*>(&s_v[m * 128 + d0]);
            float4 bv1 = *reinterpret_cast<const float4*>(&s_v[m * 128 + d0 + 4]);
            float bb[8] = {bv0.x, bv0.y, bv0.z, bv0.w, bv1.x, bv1.y, bv1.z, bv1.w};
            float a0 = s_a[(h * 64 + n0 + 0) * 65 + m];
            float a1 = s_a[(h * 64 + n0 + 1) * 65 + m];
            float a2 = s_a[(h * 64 + n0 + 2) * 65 + m];
            float a3 = s_a[(h * 64 + n0 + 3) * 65 + m];
#pragma unroll
            for (int j = 0; j < 8; j++) {
                acc[0][j] += a0 * bb[j];
                acc[1][j] += a1 * bb[j];
                acc[2][j] += a2 * bb[j];
                acc[3][j] += a3 * bb[j];
            }
        }
#pragma unroll
        for (int i = 0; i < 4; i++) {
            float4 w0 = make_float4(acc[i][0], acc[i][1], acc[i][2], acc[i][3]);
            float4 w1 = make_float4(acc[i][4], acc[i][5], acc[i][6], acc[i][7]);
            *reinterpret_cast<float4*>(&o[base + (n0 + i) * 128 + d0]) = w0;
            *reinterpret_cast<float4*>(&o[base + (n0 + i) * 128 + d0 + 4]) = w1;
        }
    }
}

// =====================================================================
// Host side
// =====================================================================
static constexpr int S128 = (64 * 129 + 128 * 128 + 64 * 128) * 4;  // 131328
static constexpr int S256 = (64 * 257 + 256 * 128 + 64 * 128) * 4;  // 229632
static constexpr int SATT = (128 * 65 * 2 + 64 * 128 + 128 * 65) * 4;  // 132608

extern "C" void kernel_launch(void* const* d_in, const int* in_sizes, int n_in,
                              void* d_out, int out_size) {
    const float* x  = (const float*)d_in[0];
    const float* mx = (const float*)d_in[1];
    const float* Wq = (const float*)d_in[2];
    const float* Wk = (const float*)d_in[3];
    const float* Wv = (const float*)d_in[4];
    const float* Wo = (const float*)d_in[5];
    const float* W1 = (const float*)d_in[6];
    const float* W2 = (const float*)d_in[7];
    float* out = (float*)d_out;

    void *p_mlp, *p_q, *p_k, *p_v, *p_o, *p_xg, *p_h1;
    cudaGetSymbolAddress(&p_mlp, g_mlp);
    cudaGetSymbolAddress(&p_q, g_q);
    cudaGetSymbolAddress(&p_k, g_k);
    cudaGetSymbolAddress(&p_v, g_v);
    cudaGetSymbolAddress(&p_o, g_o);
    cudaGetSymbolAddress(&p_xg, g_xg);
    cudaGetSymbolAddress(&p_h1, g_h1);

    cudaFuncSetAttribute(k_gemm_lif<128, 0>, cudaFuncAttributeMaxDynamicSharedMemorySize, S128);
    cudaFuncSetAttribute(k_gemm_lif<128, 1>, cudaFuncAttributeMaxDynamicSharedMemorySize, S128);
    cudaFuncSetAttribute(k_gemm_lif<256, 1>, cudaFuncAttributeMaxDynamicSharedMemorySize, S256);
    cudaFuncSetAttribute(k_attn, cudaFuncAttributeMaxDynamicSharedMemorySize, SATT);

    const int GBN = B_ * N_;  // 4096
    k_dct<<<64, 64>>>();
    k_mix<<<GBN, 128>>>(x, mx);
    // q = LIF(x @ Wq); k = LIF(mlp @ Wk); v = LIF(mlp @ Wv)
    k_gemm_lif<128, 0><<<GBN, 256, S128>>>(x, Wq, 128, 0, (float*)p_q, 128, 0, nullptr);
    k_gemm_lif<128, 0><<<GBN, 256, S128>>>((const float*)p_mlp, Wk, 128, 0, (float*)p_k, 128, 0, nullptr);
    k_gemm_lif<128, 0><<<GBN, 256, S128>>>((const float*)p_mlp, Wv, 128, 0, (float*)p_v, 128, 0, nullptr);
    // attention (exact in fp32)
    k_attn<<<T_ * B_, 256, SATT>>>((const float*)p_q, (const float*)p_k, (const float*)p_v, (float*)p_o);
    // xg = x * (1 - LIF(o @ Wo))
    k_gemm_lif<128, 1><<<GBN, 256, S128>>>((const float*)p_o, Wo, 128, 0, (float*)p_xg, 128, 0, x);
    // h1 = LIF(xg @ W1)  (two column halves of HID=256)
    k_gemm_lif<128, 0><<<GBN, 256, S128>>>((const float*)p_xg, W1, HID_, 0, (float*)p_h1, HID_, 0, nullptr);
    k_gemm_lif<128, 0><<<GBN, 256, S128>>>((const float*)p_xg, W1, HID_, 128, (float*)p_h1, HID_, 128, nullptr);
    // out = xg * (1 - LIF(h1 @ W2))
    k_gemm_lif<256, 1><<<GBN, 256, S256>>>((const float*)p_h1, W2, 128, 0, out, 128, 0, (float*)p_xg);
}

// round 2
// speedup vs baseline: 1.5191x; 1.5191x over previous
#include <cuda_runtime.h>

typedef unsigned long long ull;

constexpr int T_ = 64, B_ = 64, N_ = 64, D_ = 128, HID_ = 256;
constexpr int BND = B_ * N_ * D_;                      // 524288
constexpr size_t TOT  = (size_t)T_ * BND;              // 33554432
constexpr size_t TOTH = (size_t)T_ * B_ * N_ * HID_;   // 67108864

// -------- scratch (no allocations allowed) --------
__device__ float g_M[64 * 64];
__device__ ull   g_Mp[32 * 64];     // packed (M[2t2][s], M[2t2+1][s])
__device__ float g_mlp[TOT];
__device__ float g_q[TOT];
__device__ float g_k[TOT];
__device__ float g_v[TOT];
__device__ float g_o[TOT];
__device__ float g_xg[TOT];
__device__ float g_h1[TOTH];

// -------- packed fp32x2 helpers (Blackwell FFMA2) --------
__device__ __forceinline__ void ffma2(ull& d, ull a, ull b) {
    asm("fma.rn.f32x2 %0, %1, %2, %0;" : "+l"(d) : "l"(a), "l"(b));
}
__device__ __forceinline__ ull dup2(float x) {
    ull r; unsigned u = __float_as_uint(x);
    asm("mov.b64 %0, {%1, %1};" : "=l"(r) : "r"(u));
    return r;
}
__device__ __forceinline__ ull pack2(float lo, float hi) {
    ull r;
    asm("mov.b64 %0, {%1, %2};" : "=l"(r) : "r"(__float_as_uint(lo)), "r"(__float_as_uint(hi)));
    return r;
}

// =====================================================================
// Kernel 0: DCT lowpass operator M = C[:16]^T C[:16]  (64x64)
// =====================================================================
__global__ void k_dct() {
    int t = blockIdx.x, s = threadIdx.x;
    const double PI = 3.141592653589793238462643383279502884;
    double acc = 0.0;
    for (int kk = 0; kk < 16; kk++) {
        double scale = (kk == 0) ? sqrt(1.0 / 64.0) : sqrt(2.0 / 64.0);
        float ct = (float)(cos(PI * (t + 0.5) * kk / 64.0) * scale);
        float cs = (float)(cos(PI * (s + 0.5) * kk / 64.0) * scale);
        acc += (double)ct * (double)cs;
    }
    g_M[t * 64 + s] = (float)acc;
}
__global__ void k_pack() {
    int t2 = blockIdx.x, s = threadIdx.x;
    g_Mp[t2 * 64 + s] = pack2(g_M[(2 * t2) * 64 + s], g_M[(2 * t2 + 1) * 64 + s]);
}

// =====================================================================
// Kernel 1: memory mix + temporal lowpass (f32x2, t-paired).
// =====================================================================
__global__ void __launch_bounds__(128) k_mix(const float* __restrict__ x,
                                             const float* __restrict__ mx) {
    __shared__ float s_p[64 * 128];   // 32 KB
    __shared__ ull  s_Mp[32 * 64];    // 16 KB
    const int bn = blockIdx.x;
    const int b = bn >> 6, n = bn & 63;
    const int tid = threadIdx.x;

    for (int i = tid; i < 2048; i += 128) s_Mp[i] = g_Mp[i];

    const float* xb = x + (size_t)(b * N_ + n) * D_;
    const float* mb = mx + ((size_t)(n * B_ + b) * T_) * D_;
    for (int i = tid; i < 8192; i += 128) {
        int s = i >> 7, d = i & 127;
        float mv = mb[i];
        float mv2 = __fadd_rn(__fmul_rn(0.05f, mv), __fmul_rn(0.95f, mv));
        s_p[i] = __fmul_rn(xb[(size_t)s * BND + d], mv2);
        (void)s;
    }
    __syncthreads();

    const int d = tid;
    ull acc[32];
#pragma unroll
    for (int t2 = 0; t2 < 32; t2++) acc[t2] = 0ull;

    for (int s = 0; s < 64; s++) {
        ull cp = dup2(s_p[s * 128 + d]);
#pragma unroll
        for (int t2 = 0; t2 < 32; t2++) ffma2(acc[t2], s_Mp[t2 * 64 + s], cp);
    }

    float* ob = g_mlp + (size_t)(b * N_ + n) * D_ + d;
#pragma unroll
    for (int t2 = 0; t2 < 32; t2++) {
        float2 f = *reinterpret_cast<float2*>(&acc[t2]);
        ob[(size_t)(2 * t2) * BND] = f.x;
        ob[(size_t)(2 * t2 + 1) * BND] = f.y;
    }
}

// =====================================================================
// GEMM + fused LIF. 2 (b,n) tiles per CTA (128 rows x 128 cols), f32x2.
// K handled in chunks of 128 (KCHUNKS). MODE 0: spikes; MODE 1: gx*(1-spk).
// =====================================================================
constexpr int MPAD = 130;
static constexpr int SGEMM = (128 * MPAD + 128 * 128 + 128 * 128) * 4;  // 197632

template <int KCHUNKS, int MODE>
__global__ void __launch_bounds__(256) k_gemm2(
    const float* __restrict__ in, const float* __restrict__ W, int ldw, int wcol0,
    float* __restrict__ out, int ldo, int ocol0, const float* __restrict__ gx) {
    extern __shared__ float sm[];
    float* s_inT = sm;                       // [128 r][MPAD m]  (transposed)
    float* s_W   = sm + 128 * MPAD;          // [128 r][128 c]
    float* s_pre = s_W + 128 * 128;          // [128 m][128 c]
    const int bn0 = blockIdx.x * 2;
    const int tid = threadIdx.x;
    constexpr int DIN = KCHUNKS * 128;
    const size_t istride = (size_t)4096 * DIN;

    const int c0 = (tid & 15) << 3;
    const int m0 = (tid >> 4) << 3;
    ull acc[4][8];
#pragma unroll
    for (int i = 0; i < 4; i++)
#pragma unroll
        for (int j = 0; j < 8; j++) acc[i][j] = 0ull;

    for (int ch = 0; ch < KCHUNKS; ch++) {
        if (ch) __syncthreads();
        for (int i = tid; i < 128 * 128; i += 256) {
            int c = i & 127, r = i >> 7;
            s_W[r * 128 + c] = W[(size_t)(ch * 128 + r) * ldw + wcol0 + c];
        }
        for (int i = tid; i < 128 * 128; i += 256) {
            int r = i & 127, m = i >> 7;
            int tile = m >> 6, t = m & 63;
            s_inT[r * MPAD + m] =
                in[(size_t)t * istride + (size_t)(bn0 + tile) * DIN + ch * 128 + r];
        }
        __syncthreads();

#pragma unroll 2
        for (int r = 0; r < 128; r++) {
            ull a[4];
#pragma unroll
            for (int i = 0; i < 4; i++)
                a[i] = *reinterpret_cast<const ull*>(&s_inT[r * MPAD + m0 + 2 * i]);
            float4 b0 = *reinterpret_cast<const float4*>(&s_W[r * 128 + c0]);
            float4 b1 = *reinterpret_cast<const float4*>(&s_W[r * 128 + c0 + 4]);
            ull bp[8];
            bp[0] = dup2(b0.x); bp[1] = dup2(b0.y); bp[2] = dup2(b0.z); bp[3] = dup2(b0.w);
            bp[4] = dup2(b1.x); bp[5] = dup2(b1.y); bp[6] = dup2(b1.z); bp[7] = dup2(b1.w);
#pragma unroll
            for (int i = 0; i < 4; i++)
#pragma unroll
                for (int j = 0; j < 8; j++) ffma2(acc[i][j], a[i], bp[j]);
        }
    }

#pragma unroll
    for (int i = 0; i < 4; i++)
#pragma unroll
        for (int j = 0; j < 8; j++) {
            float2 f = *reinterpret_cast<float2*>(&acc[i][j]);
            s_pre[(m0 + 2 * i) * 128 + c0 + j] = f.x;
            s_pre[(m0 + 2 * i + 1) * 128 + c0 + j] = f.y;
        }
    __syncthreads();

    // LIF scan: 256 threads = 2 tiles x 128 columns
    {
        const int tile = tid >> 7, c = tid & 127;
        const int bn = bn0 + tile;
        float vmem = 0.f;
        const size_t ostride = (size_t)4096 * ldo;
        const size_t obase = (size_t)bn * ldo + ocol0 + c;
        const size_t gbase = (size_t)bn * 128 + c;
#pragma unroll 1
        for (int t = 0; t < 64; t++) {
            float p = s_pre[(tile * 64 + t) * 128 + c];
            vmem = __fadd_rn(vmem, __fmul_rn(__fsub_rn(p, vmem), 0.5f));
            float spk = (vmem >= 1.0f) ? 1.0f : 0.0f;
            if (vmem >= 1.0f) vmem = 0.0f;
            size_t oi = obase + (size_t)t * ostride;
            if (MODE == 0) {
                out[oi] = spk;
            } else {
                float g = gx[gbase + (size_t)t * (size_t)BND];
                out[oi] = __fmul_rn(g, __fsub_rn(1.0f, spk));
            }
        }
    }
}

// =====================================================================
// Attention per (t,b): phase1 via bitpack+POPC (exact), phase2 f32x2.
// =====================================================================
static constexpr int SATT = (8192 + 128 * 68) * 4 + 2 * 256 * 4;  // 69632

__global__ void __launch_bounds__(256) k_attn2(const float* __restrict__ q,
                                               const float* __restrict__ k,
                                               const float* __restrict__ v,
                                               float* __restrict__ o) {
    extern __shared__ float sma[];
    float* s_v = sma;                                   // 64 m x 128 d
    float* s_a = sma + 8192;                            // [128 hn][68 m] / staging
    unsigned* s_qmu = (unsigned*)(sma + 8192 + 128 * 68);  // 256
    unsigned* s_kmu = s_qmu + 256;                         // 256
    const int tb = blockIdx.x;
    const size_t base = (size_t)tb * 8192;
    const int tid = threadIdx.x;
    const int w = tid >> 5, lane = tid & 31;

    for (int i = tid; i < 8192; i += 256) { s_v[i] = v[base + i]; s_a[i] = q[base + i]; }
    __syncthreads();
    for (int j = w; j < 128; j += 8) {      // j = h*64 + n
        int n = j & 63, h = j >> 6;
        float v0 = s_a[n * 128 + h * 64 + lane];
        float v1 = s_a[n * 128 + h * 64 + 32 + lane];
        unsigned lo = __ballot_sync(0xffffffffu, v0 > 0.5f);
        unsigned hi = __ballot_sync(0xffffffffu, v1 > 0.5f);
        if (lane == 0) { s_qmu[j * 2] = lo; s_qmu[j * 2 + 1] = hi; }
    }
    __syncthreads();
    for (int i = tid; i < 8192; i += 256) s_a[i] = k[base + i];
    __syncthreads();
    for (int j = w; j < 128; j += 8) {
        int n = j & 63, h = j >> 6;
        float v0 = s_a[n * 128 + h * 64 + lane];
        float v1 = s_a[n * 128 + h * 64 + 32 + lane];
        unsigned lo = __ballot_sync(0xffffffffu, v0 > 0.5f);
        unsigned hi = __ballot_sync(0xffffffffu, v1 > 0.5f);
        if (lane == 0) { s_kmu[j * 2] = lo; s_kmu[j * 2 + 1] = hi; }
    }
    __syncthreads();

    // phase 1: attn[hn][m] = 0.125 * popc(qmask[hn] & kmask[h*64+m])
    {
        const ull* qm = (const ull*)s_qmu;
        const ull* km = (const ull*)s_kmu;
        const int hn = tid >> 1;
        const int mb0 = (tid & 1) * 32;
        const int hbase = (hn >> 6) << 6;
        ull qv = qm[hn];
#pragma unroll
        for (int mm = 0; mm < 32; mm++) {
            int m = mb0 + mm;
            s_a[hn * 68 + m] = 0.125f * (float)__popcll(qv & km[hbase + m]);
        }
    }
    __syncthreads();

    // phase 2: o[n][d] = sum_m attn * v   (f32x2, pairs along d)
    {
        const int n0 = (tid >> 4) << 2;
        const int d0 = (tid & 15) << 3;
        const int h = d0 >> 6;
        ull acc[4][4];
#pragma unroll
        for (int i = 0; i < 4; i++)
#pragma unroll
            for (int p = 0; p < 4; p++) acc[i][p] = 0ull;
        for (int m = 0; m < 64; m++) {
            ulonglong2 vv0 = *reinterpret_cast<const ulonglong2*>(&s_v[m * 128 + d0]);
            ulonglong2 vv1 = *reinterpret_cast<const ulonglong2*>(&s_v[m * 128 + d0 + 4]);
            ull vp[4] = {vv0.x, vv0.y, vv1.x, vv1.y};
#pragma unroll
            for (int i = 0; i < 4; i++) {
                ull ap = dup2(s_a[(h * 64 + n0 + i) * 68 + m]);
#pragma unroll
                for (int p = 0; p < 4; p++) ffma2(acc[i][p], ap, vp[p]);
            }
        }
#pragma unroll
        for (int i = 0; i < 4; i++) {
            ull* op = reinterpret_cast<ull*>(&o[base + (size_t)(n0 + i) * 128 + d0]);
            op[0] = acc[i][0]; op[1] = acc[i][1]; op[2] = acc[i][2]; op[3] = acc[i][3];
        }
    }
}

// =====================================================================
// Host side
// =====================================================================
extern "C" void kernel_launch(void* const* d_in, const int* in_sizes, int n_in,
                              void* d_out, int out_size) {
    const float* x  = (const float*)d_in[0];
    const float* mx = (const float*)d_in[1];
    const float* Wq = (const float*)d_in[2];
    const float* Wk = (const float*)d_in[3];
    const float* Wv = (const float*)d_in[4];
    const float* Wo = (const float*)d_in[5];
    const float* W1 = (const float*)d_in[6];
    const float* W2 = (const float*)d_in[7];
    float* out = (float*)d_out;

    void *p_mlp, *p_q, *p_k, *p_v, *p_o, *p_xg, *p_h1;
    cudaGetSymbolAddress(&p_mlp, g_mlp);
    cudaGetSymbolAddress(&p_q, g_q);
    cudaGetSymbolAddress(&p_k, g_k);
    cudaGetSymbolAddress(&p_v, g_v);
    cudaGetSymbolAddress(&p_o, g_o);
    cudaGetSymbolAddress(&p_xg, g_xg);
    cudaGetSymbolAddress(&p_h1, g_h1);

    cudaFuncSetAttribute(k_gemm2<1, 0>, cudaFuncAttributeMaxDynamicSharedMemorySize, SGEMM);
    cudaFuncSetAttribute(k_gemm2<1, 1>, cudaFuncAttributeMaxDynamicSharedMemorySize, SGEMM);
    cudaFuncSetAttribute(k_gemm2<2, 1>, cudaFuncAttributeMaxDynamicSharedMemorySize, SGEMM);
    cudaFuncSetAttribute(k_attn2, cudaFuncAttributeMaxDynamicSharedMemorySize, SATT);

    k_dct<<<64, 64>>>();
    k_pack<<<32, 64>>>();
    k_mix<<<4096, 128>>>(x, mx);
    // q = LIF(x @ Wq); k = LIF(mlp @ Wk); v = LIF(mlp @ Wv)
    k_gemm2<1, 0><<<2048, 256, SGEMM>>>(x, Wq, 128, 0, (float*)p_q, 128, 0, nullptr);
    k_gemm2<1, 0><<<2048, 256, SGEMM>>>((const float*)p_mlp, Wk, 128, 0, (float*)p_k, 128, 0, nullptr);
    k_gemm2<1, 0><<<2048, 256, SGEMM>>>((const float*)p_mlp, Wv, 128, 0, (float*)p_v, 128, 0, nullptr);
    // attention
    k_attn2<<<4096, 256, SATT>>>((const float*)p_q, (const float*)p_k, (const float*)p_v, (float*)p_o);
    // xg = x * (1 - LIF(o @ Wo))
    k_gemm2<1, 1><<<2048, 256, SGEMM>>>((const float*)p_o, Wo, 128, 0, (float*)p_xg, 128, 0, x);
    // h1 = LIF(xg @ W1)  (two column halves)
    k_gemm2<1, 0><<<2048, 256, SGEMM>>>((const float*)p_xg, W1, 256, 0, (float*)p_h1, 256, 0, nullptr);
    k_gemm2<1, 0><<<2048, 256, SGEMM>>>((const float*)p_xg, W1, 256, 128, (float*)p_h1, 256, 128, nullptr);
    // out = xg * (1 - LIF(h1 @ W2))
    k_gemm2<2, 1><<<2048, 256, SGEMM>>>((const float*)p_h1, W2, 128, 0, out, 128, 0, (float*)p_xg);
}

// round 4
// speedup vs baseline: 2.0834x; 1.3715x over previous
#include <cuda_runtime.h>
#include <cuda_bf16.h>
#include <cstdint>

typedef unsigned long long ull;

constexpr int T_ = 64, B_ = 64, N_ = 64, D_ = 128, HID_ = 256;
constexpr int BND = B_ * N_ * D_;                      // 524288
constexpr size_t TOT  = (size_t)T_ * BND;              // 33554432
constexpr size_t TOTH = (size_t)T_ * B_ * N_ * HID_;   // 67108864

// -------- scratch (no allocations allowed) --------
__device__ float g_M[64 * 64];
__device__ ull   g_Mp[32 * 64];
__device__ float g_mlp[TOT];
__device__ float g_q[TOT];
__device__ float g_k[TOT];
__device__ float g_v[TOT];
__device__ float g_o[TOT];
__device__ float g_xg[TOT];
__device__ float g_h1[TOTH];
// weight splits: 7 tiles (q,k,v,o,w1a,w1b,w2), each [3 splits][128 n][K<=256 k] bf16
__device__ __nv_bfloat16 g_wsp[7][3 * 128 * 256];

// -------- small helpers --------
__device__ __forceinline__ void ffma2(ull& d, ull a, ull b) {
    asm("fma.rn.f32x2 %0, %1, %2, %0;" : "+l"(d) : "l"(a), "l"(b));
}
__device__ __forceinline__ ull dup2(float x) {
    ull r; unsigned u = __float_as_uint(x);
    asm("mov.b64 %0, {%1, %1};" : "=l"(r) : "r"(u));
    return r;
}
__device__ __forceinline__ ull pack2(float lo, float hi) {
    ull r;
    asm("mov.b64 %0, {%1, %2};" : "=l"(r) : "r"(__float_as_uint(lo)), "r"(__float_as_uint(hi)));
    return r;
}
__device__ __forceinline__ uint32_t smem_u32(const void* p) {
    uint32_t a;
    asm("{ .reg .u64 t; cvta.to.shared.u64 t, %1; cvt.u32.u64 %0, t; }" : "=r"(a) : "l"(p));
    return a;
}
__device__ __forceinline__ uint32_t sw128(uint32_t off) { return off ^ ((off >> 3) & 0x70); }

__device__ __forceinline__ void ldsm4(uint32_t* r, uint32_t addr) {
    asm volatile("ldmatrix.sync.aligned.m8n8.x4.shared.b16 {%0,%1,%2,%3}, [%4];"
                 : "=r"(r[0]), "=r"(r[1]), "=r"(r[2]), "=r"(r[3]) : "r"(addr));
}
__device__ __forceinline__ void mma16816(float* d, const uint32_t* a, uint32_t b0, uint32_t b1) {
    asm volatile(
        "mma.sync.aligned.m16n8k16.row.col.f32.bf16.bf16.f32 "
        "{%0,%1,%2,%3}, {%4,%5,%6,%7}, {%8,%9}, {%0,%1,%2,%3};"
        : "+f"(d[0]), "+f"(d[1]), "+f"(d[2]), "+f"(d[3])
        : "r"(a[0]), "r"(a[1]), "r"(a[2]), "r"(a[3]), "r"(b0), "r"(b1));
}

// =====================================================================
// DCT operator M = C[:16]^T C[:16] and its packed form
// =====================================================================
__global__ void k_dct() {
    int t = blockIdx.x, s = threadIdx.x;
    const double PI = 3.141592653589793238462643383279502884;
    double acc = 0.0;
    for (int kk = 0; kk < 16; kk++) {
        double scale = (kk == 0) ? sqrt(1.0 / 64.0) : sqrt(2.0 / 64.0);
        float ct = (float)(cos(PI * (t + 0.5) * kk / 64.0) * scale);
        float cs = (float)(cos(PI * (s + 0.5) * kk / 64.0) * scale);
        acc += (double)ct * (double)cs;
    }
    g_M[t * 64 + s] = (float)acc;
}
__global__ void k_pack() {
    int t2 = blockIdx.x, s = threadIdx.x;
    g_Mp[t2 * 64 + s] = pack2(g_M[(2 * t2) * 64 + s], g_M[(2 * t2 + 1) * 64 + s]);
}

// =====================================================================
// Weight split: W[k, wcol0+n] -> out[s][n][k] bf16 (3-way split, [N,K])
// =====================================================================
__global__ void k_wsplit(const float* __restrict__ W, int ldw, int wcol0, int K,
                         __nv_bfloat16* __restrict__ out) {
    int idx = blockIdx.x * 256 + threadIdx.x;
    if (idx >= 128 * K) return;
    int n = idx / K, k = idx - n * K;
    float w = W[(size_t)k * ldw + wcol0 + n];
    __nv_bfloat16 hi = __float2bfloat16(w);
    float r1 = __fsub_rn(w, __bfloat162float(hi));
    __nv_bfloat16 mid = __float2bfloat16(r1);
    float r2 = __fsub_rn(r1, __bfloat162float(mid));
    __nv_bfloat16 lo = __float2bfloat16(r2);
    out[(size_t)(0 * 128 + n) * K + k] = hi;
    out[(size_t)(1 * 128 + n) * K + k] = mid;
    out[(size_t)(2 * 128 + n) * K + k] = lo;
}

// =====================================================================
// Memory mix + temporal lowpass (FFMA2)
// =====================================================================
__global__ void __launch_bounds__(128) k_mix(const float* __restrict__ x,
                                             const float* __restrict__ mx) {
    __shared__ float s_p[64 * 128];
    __shared__ ull  s_Mp[32 * 64];
    const int bn = blockIdx.x;
    const int b = bn >> 6, n = bn & 63;
    const int tid = threadIdx.x;

    for (int i = tid; i < 2048; i += 128) s_Mp[i] = g_Mp[i];

    const float* xb = x + (size_t)(b * N_ + n) * D_;
    const float* mb = mx + ((size_t)(n * B_ + b) * T_) * D_;
    for (int i = tid; i < 8192; i += 128) {
        float mv = mb[i];
        float mv2 = __fadd_rn(__fmul_rn(0.05f, mv), __fmul_rn(0.95f, mv));
        s_p[i] = __fmul_rn(xb[(size_t)(i >> 7) * BND + (i & 127)], mv2);
    }
    __syncthreads();

    const int d = tid;
    ull acc[32];
#pragma unroll
    for (int t2 = 0; t2 < 32; t2++) acc[t2] = 0ull;
    for (int s = 0; s < 64; s++) {
        ull cp = dup2(s_p[s * 128 + d]);
#pragma unroll
        for (int t2 = 0; t2 < 32; t2++) ffma2(acc[t2], s_Mp[t2 * 64 + s], cp);
    }
    float* ob = g_mlp + (size_t)(b * N_ + n) * D_ + d;
#pragma unroll
    for (int t2 = 0; t2 < 32; t2++) {
        float2 f = *reinterpret_cast<float2*>(&acc[t2]);
        ob[(size_t)(2 * t2) * BND] = f.x;
        ob[(size_t)(2 * t2 + 1) * BND] = f.y;
    }
}

// =====================================================================
// Tensor-core GEMM (mma.sync bf16) + fused LIF.
// Per CTA: 2 (b,n) tiles -> M=128 rows, N=128 cols, register accumulate.
// Tiles: per (split, khalf): [128 rows][64 k] bf16, 128B rows, SW128.
// =====================================================================
constexpr int OFF_A = 1024;
constexpr int OFF_B = 1024 + 6 * 16384;
constexpr int SGEMM = 1024 + 12 * 16384;   // 197632 bytes
constexpr int PPAD = 130;

template <int KCHUNKS, int MODE, int ASPLITS>
__global__ void __launch_bounds__(256) k_mmag(
    const float* __restrict__ in, const __nv_bfloat16* __restrict__ wsp,
    float* __restrict__ out, int ldo, int ocol0, const float* __restrict__ gx) {
    extern __shared__ __align__(16) char smem_raw[];
    const uint32_t sbase = smem_u32(smem_raw);
    float* s_pre = (float*)(smem_raw + OFF_A);   // reuse A region after MMAs
    const int bn0 = blockIdx.x * 2;
    const int tid = threadIdx.x;
    const int wid = tid >> 5, lane = tid & 31;
    constexpr int KTOT = KCHUNKS * 128;

    // warp tile: 2 (m) x 4 (n) warps; warp tile 64m x 32n
    const int m_base = (wid & 1) * 64;
    const int n_base = (wid >> 1) * 32;
    const int sub = lane >> 3, lr = lane & 7;
    const int arow_off = (sub & 1) * 8 + lr;     // A: r0=m0 k0, r1=m+8 k0, r2=m0 k+8, r3=m+8 k+8
    const int akc = (sub >> 1) * 8;
    const int brow_off = (sub >> 1) * 8 + lr;    // B: r0=n0 k0, r1=n0 k+8, r2=n+8 k0, r3=n+8 k+8
    const int bkc = (sub & 1) * 8;

    float acc[4][4][4];
#pragma unroll
    for (int i = 0; i < 4; i++)
#pragma unroll
        for (int j = 0; j < 4; j++)
#pragma unroll
            for (int e = 0; e < 4; e++) acc[i][j][e] = 0.f;

    for (int ch = 0; ch < KCHUNKS; ch++) {
        if (ch) __syncthreads();
        // ---- load B splits (bf16, pre-transposed [n][k]) with SW128 swizzle ----
        for (int u = tid; u < 6144; u += 256) {
            int s = u >> 11;
            int r = u & 2047;
            int n = r >> 4, kg = r & 15;
            int kh = kg >> 3, gsub = kg & 7;
            const __nv_bfloat16* src =
                wsp + ((size_t)(s * 128 + n) * KTOT + ch * 128 + kh * 64 + gsub * 8);
            uint4 val = *reinterpret_cast<const uint4*>(src);
            uint32_t off = sw128((n << 7) + (gsub << 4));
            *reinterpret_cast<uint4*>(smem_raw + OFF_B + (s * 2 + kh) * 16384 + off) = val;
        }
        // ---- load + split-convert A ----
        for (int u = tid; u < 2048; u += 256) {
            int m = u >> 4, kg = u & 15;
            int kh = kg >> 3, gsub = kg & 7;
            int t = m & 63, tile = m >> 6;
            const float* src = in + (size_t)t * ((size_t)4096 * KTOT)
                                  + (size_t)(bn0 + tile) * KTOT + ch * 128 + kh * 64 + gsub * 8;
            float4 f0 = *reinterpret_cast<const float4*>(src);
            float4 f1 = *reinterpret_cast<const float4*>(src + 4);
            float a[8] = {f0.x, f0.y, f0.z, f0.w, f1.x, f1.y, f1.z, f1.w};
            __align__(16) __nv_bfloat16 hi[8], mid[8], lo[8];
#pragma unroll
            for (int e = 0; e < 8; e++) {
                hi[e] = __float2bfloat16(a[e]);
                if (ASPLITS >= 2) {
                    float r1 = __fsub_rn(a[e], __bfloat162float(hi[e]));
                    mid[e] = __float2bfloat16(r1);
                    if (ASPLITS >= 3) {
                        float r2 = __fsub_rn(r1, __bfloat162float(mid[e]));
                        lo[e] = __float2bfloat16(r2);
                    }
                }
            }
            uint32_t off = sw128((m << 7) + (gsub << 4));
            *reinterpret_cast<uint4*>(smem_raw + OFF_A + (0 * 2 + kh) * 16384 + off) =
                *reinterpret_cast<uint4*>(hi);
            if (ASPLITS >= 2)
                *reinterpret_cast<uint4*>(smem_raw + OFF_A + (1 * 2 + kh) * 16384 + off) =
                    *reinterpret_cast<uint4*>(mid);
            if (ASPLITS >= 3)
                *reinterpret_cast<uint4*>(smem_raw + OFF_A + (2 * 2 + kh) * 16384 + off) =
                    *reinterpret_cast<uint4*>(lo);
        }
        __syncthreads();

        // ---- split-pass schedule ----
        const int NP = (ASPLITS == 3) ? 6 : (ASPLITS == 2 ? 5 : 3);
        const int PAs[6] = {0, 0, 1, 0, 1, 2};
        const int PBs[6] = {0, 1, 0, 2, 1, 0};
        const int PA1[6] = {0, 0, 0, 0, 0, 0};
        const int PB1[6] = {0, 1, 2, 0, 0, 0};

        for (int p = 0; p < NP; p++) {
            int As = (ASPLITS == 1) ? PA1[p] : PAs[p];
            int Bs = (ASPLITS == 1) ? PB1[p] : PBs[p];
#pragma unroll
            for (int kh = 0; kh < 2; kh++) {
                uint32_t Abase = sbase + OFF_A + (As * 2 + kh) * 16384;
                uint32_t Bbase = sbase + OFF_B + (Bs * 2 + kh) * 16384;
#pragma unroll
                for (int ks = 0; ks < 4; ks++) {
                    int k0 = ks * 16;
                    uint32_t afr[4][4];
#pragma unroll
                    for (int mf = 0; mf < 4; mf++)
                        ldsm4(afr[mf], Abase +
                              sw128(((m_base + mf * 16 + arow_off) << 7) + (k0 + akc) * 2));
                    uint32_t bfr[2][4];
#pragma unroll
                    for (int nf2 = 0; nf2 < 2; nf2++)
                        ldsm4(bfr[nf2], Bbase +
                              sw128(((n_base + nf2 * 16 + brow_off) << 7) + (k0 + bkc) * 2));
#pragma unroll
                    for (int mf = 0; mf < 4; mf++)
#pragma unroll
                        for (int nf = 0; nf < 4; nf++)
                            mma16816(acc[mf][nf], afr[mf],
                                     bfr[nf >> 1][(nf & 1) * 2], bfr[nf >> 1][(nf & 1) * 2 + 1]);
                }
            }
        }
    }
    __syncthreads();   // all warps done reading tiles; A region becomes s_pre

    // ---- store fragments to s_pre ----
    {
        const int qr = lane >> 2, qc = (lane & 3) * 2;
#pragma unroll
        for (int mf = 0; mf < 4; mf++)
#pragma unroll
            for (int nf = 0; nf < 4; nf++) {
                int row = m_base + mf * 16 + qr;
                int col = n_base + nf * 8 + qc;
                *reinterpret_cast<float2*>(&s_pre[row * PPAD + col]) =
                    make_float2(acc[mf][nf][0], acc[mf][nf][1]);
                *reinterpret_cast<float2*>(&s_pre[(row + 8) * PPAD + col]) =
                    make_float2(acc[mf][nf][2], acc[mf][nf][3]);
            }
    }
    __syncthreads();

    // ---- fused LIF scan over time (2 tiles x 128 cols) ----
    {
        const int tile = tid >> 7, c = tid & 127;
        const int bn = bn0 + tile;
        float vmem = 0.f;
        const size_t ostride = (size_t)4096 * ldo;
        const size_t obase = (size_t)bn * ldo + ocol0 + c;
        const size_t gbase = (size_t)bn * 128 + c;
#pragma unroll 1
        for (int t = 0; t < 64; t++) {
            float p = s_pre[(tile * 64 + t) * PPAD + c];
            vmem = __fadd_rn(vmem, __fmul_rn(__fsub_rn(p, vmem), 0.5f));
            float spk = (vmem >= 1.0f) ? 1.0f : 0.0f;
            if (vmem >= 1.0f) vmem = 0.0f;
            size_t oi = obase + (size_t)t * ostride;
            if (MODE == 0) {
                out[oi] = spk;
            } else {
                float g = gx[gbase + (size_t)t * (size_t)BND];
                out[oi] = __fmul_rn(g, __fsub_rn(1.0f, spk));
            }
        }
    }
}

// =====================================================================
// Attention: phase1 bitpack+POPC (exact), phase2 f32x2
// =====================================================================
static constexpr int SATT = (8192 + 128 * 68) * 4 + 2 * 256 * 4;

__global__ void __launch_bounds__(256) k_attn2(const float* __restrict__ q,
                                               const float* __restrict__ k,
                                               const float* __restrict__ v,
                                               float* __restrict__ o) {
    extern __shared__ float sma[];
    float* s_v = sma;
    float* s_a = sma + 8192;
    unsigned* s_qmu = (unsigned*)(sma + 8192 + 128 * 68);
    unsigned* s_kmu = s_qmu + 256;
    const int tb = blockIdx.x;
    const size_t base = (size_t)tb * 8192;
    const int tid = threadIdx.x;
    const int w = tid >> 5, lane = tid & 31;

    for (int i = tid; i < 8192; i += 256) { s_v[i] = v[base + i]; s_a[i] = q[base + i]; }
    __syncthreads();
    for (int j = w; j < 128; j += 8) {
        int n = j & 63, h = j >> 6;
        float v0 = s_a[n * 128 + h * 64 + lane];
        float v1 = s_a[n * 128 + h * 64 + 32 + lane];
        unsigned lo = __ballot_sync(0xffffffffu, v0 > 0.5f);
        unsigned hi = __ballot_sync(0xffffffffu, v1 > 0.5f);
        if (lane == 0) { s_qmu[j * 2] = lo; s_qmu[j * 2 + 1] = hi; }
    }
    __syncthreads();
    for (int i = tid; i < 8192; i += 256) s_a[i] = k[base + i];
    __syncthreads();
    for (int j = w; j < 128; j += 8) {
        int n = j & 63, h = j >> 6;
        float v0 = s_a[n * 128 + h * 64 + lane];
        float v1 = s_a[n * 128 + h * 64 + 32 + lane];
        unsigned lo = __ballot_sync(0xffffffffu, v0 > 0.5f);
        unsigned hi = __ballot_sync(0xffffffffu, v1 > 0.5f);
        if (lane == 0) { s_kmu[j * 2] = lo; s_kmu[j * 2 + 1] = hi; }
    }
    __syncthreads();

    {
        const ull* qm = (const ull*)s_qmu;
        const ull* km = (const ull*)s_kmu;
        const int hn = tid >> 1;
        const int mb0 = (tid & 1) * 32;
        const int hbase = (hn >> 6) << 6;
        ull qv = qm[hn];
#pragma unroll
        for (int mm = 0; mm < 32; mm++) {
            int m = mb0 + mm;
            s_a[hn * 68 + m] = 0.125f * (float)__popcll(qv & km[hbase + m]);
        }
    }
    __syncthreads();

    {
        const int n0 = (tid >> 4) << 2;
        const int d0 = (tid & 15) << 3;
        const int h = d0 >> 6;
        ull acc[4][4];
#pragma unroll
        for (int i = 0; i < 4; i++)
#pragma unroll
            for (int p = 0; p < 4; p++) acc[i][p] = 0ull;
        for (int m = 0; m < 64; m++) {
            ulonglong2 vv0 = *reinterpret_cast<const ulonglong2*>(&s_v[m * 128 + d0]);
            ulonglong2 vv1 = *reinterpret_cast<const ulonglong2*>(&s_v[m * 128 + d0 + 4]);
            ull vp[4] = {vv0.x, vv0.y, vv1.x, vv1.y};
#pragma unroll
            for (int i = 0; i < 4; i++) {
                ull ap = dup2(s_a[(h * 64 + n0 + i) * 68 + m]);
#pragma unroll
                for (int p = 0; p < 4; p++) ffma2(acc[i][p], ap, vp[p]);
            }
        }
#pragma unroll
        for (int i = 0; i < 4; i++) {
            ull* op = reinterpret_cast<ull*>(&o[base + (size_t)(n0 + i) * 128 + d0]);
            op[0] = acc[i][0]; op[1] = acc[i][1]; op[2] = acc[i][2]; op[3] = acc[i][3];
        }
    }
}

// =====================================================================
// Host side
// =====================================================================
extern "C" void kernel_launch(void* const* d_in, const int* in_sizes, int n_in,
                              void* d_out, int out_size) {
    const float* x  = (const float*)d_in[0];
    const float* mx = (const float*)d_in[1];
    const float* Wq = (const float*)d_in[2];
    const float* Wk = (const float*)d_in[3];
    const float* Wv = (const float*)d_in[4];
    const float* Wo = (const float*)d_in[5];
    const float* W1 = (const float*)d_in[6];
    const float* W2 = (const float*)d_in[7];
    float* out = (float*)d_out;

    void *p_mlp, *p_q, *p_k, *p_v, *p_o, *p_xg, *p_h1, *p_wsp;
    cudaGetSymbolAddress(&p_mlp, g_mlp);
    cudaGetSymbolAddress(&p_q, g_q);
    cudaGetSymbolAddress(&p_k, g_k);
    cudaGetSymbolAddress(&p_v, g_v);
    cudaGetSymbolAddress(&p_o, g_o);
    cudaGetSymbolAddress(&p_xg, g_xg);
    cudaGetSymbolAddress(&p_h1, g_h1);
    cudaGetSymbolAddress(&p_wsp, g_wsp);
    __nv_bfloat16* wsp = (__nv_bfloat16*)p_wsp;
    const size_t WSTRIDE = 3 * 128 * 256;

    cudaFuncSetAttribute(k_mmag<1, 0, 3>, cudaFuncAttributeMaxDynamicSharedMemorySize, SGEMM);
    cudaFuncSetAttribute(k_mmag<1, 1, 2>, cudaFuncAttributeMaxDynamicSharedMemorySize, SGEMM);
    cudaFuncSetAttribute(k_mmag<2, 1, 1>, cudaFuncAttributeMaxDynamicSharedMemorySize, SGEMM);
    cudaFuncSetAttribute(k_attn2, cudaFuncAttributeMaxDynamicSharedMemorySize, SATT);

    // constants + weight splits
    k_dct<<<64, 64>>>();
    k_pack<<<32, 64>>>();
    k_wsplit<<<64, 256>>>(Wq, 128, 0, 128, wsp + 0 * WSTRIDE);
    k_wsplit<<<64, 256>>>(Wk, 128, 0, 128, wsp + 1 * WSTRIDE);
    k_wsplit<<<64, 256>>>(Wv, 128, 0, 128, wsp + 2 * WSTRIDE);
    k_wsplit<<<64, 256>>>(Wo, 128, 0, 128, wsp + 3 * WSTRIDE);
    k_wsplit<<<64, 256>>>(W1, 256, 0, 128, wsp + 4 * WSTRIDE);
    k_wsplit<<<64, 256>>>(W1, 256, 128, 128, wsp + 5 * WSTRIDE);
    k_wsplit<<<128, 256>>>(W2, 128, 0, 256, wsp + 6 * WSTRIDE);

    k_mix<<<4096, 128>>>(x, mx);
    // q = LIF(x @ Wq); k = LIF(mlp @ Wk); v = LIF(mlp @ Wv)
    k_mmag<1, 0, 3><<<2048, 256, SGEMM>>>(x, wsp + 0 * WSTRIDE, (float*)p_q, 128, 0, nullptr);
    k_mmag<1, 0, 3><<<2048, 256, SGEMM>>>((const float*)p_mlp, wsp + 1 * WSTRIDE, (float*)p_k, 128, 0, nullptr);
    k_mmag<1, 0, 3><<<2048, 256, SGEMM>>>((const float*)p_mlp, wsp + 2 * WSTRIDE, (float*)p_v, 128, 0, nullptr);
    // attention (exact)
    k_attn2<<<4096, 256, SATT>>>((const float*)p_q, (const float*)p_k, (const float*)p_v, (float*)p_o);
    // xg = x * (1 - LIF(o @ Wo))   (o exact in 2 bf16 splits)
    k_mmag<1, 1, 2><<<2048, 256, SGEMM>>>((const float*)p_o, wsp + 3 * WSTRIDE, (float*)p_xg, 128, 0, x);
    // h1 = LIF(xg @ W1)  (two N-halves)
    k_mmag<1, 0, 3><<<2048, 256, SGEMM>>>((const float*)p_xg, wsp + 4 * WSTRIDE, (float*)p_h1, 256, 0, nullptr);
    k_mmag<1, 0, 3><<<2048, 256, SGEMM>>>((const float*)p_xg, wsp + 5 * WSTRIDE, (float*)p_h1, 256, 128, nullptr);
    // out = xg * (1 - LIF(h1 @ W2))  (binary A -> single split, K=256)
    k_mmag<2, 1, 1><<<2048, 256, SGEMM>>>((const float*)p_h1, wsp + 6 * WSTRIDE, out, 128, 0, (float*)p_xg);
}

// round 5
// speedup vs baseline: 2.1076x; 1.0116x over previous
#include <cuda_runtime.h>
#include <cuda_bf16.h>
#include <cstdint>

typedef unsigned long long ull;

constexpr int T_ = 64, B_ = 64, N_ = 64, D_ = 128, HID_ = 256;
constexpr int BND = B_ * N_ * D_;                      // 524288
constexpr size_t TOT  = (size_t)T_ * BND;              // 33554432
constexpr size_t TOTH = (size_t)T_ * B_ * N_ * HID_;   // 67108864

// -------- scratch (no allocations allowed) --------
__device__ float g_M[64 * 64];
__device__ ull   g_Mp[32 * 64];
__device__ float g_mlp[TOT];
__device__ float g_q[TOT];
__device__ float g_k[TOT];
__device__ float g_v[TOT];
__device__ float g_o[TOT];
__device__ float g_xg[TOT];
__device__ float g_h1[TOTH];
__device__ __nv_bfloat16 g_wsp[7][3 * 128 * 256];

// -------- helpers --------
__device__ __forceinline__ void ffma2(ull& d, ull a, ull b) {
    asm("fma.rn.f32x2 %0, %1, %2, %0;" : "+l"(d) : "l"(a), "l"(b));
}
__device__ __forceinline__ ull dup2(float x) {
    ull r; unsigned u = __float_as_uint(x);
    asm("mov.b64 %0, {%1, %1};" : "=l"(r) : "r"(u));
    return r;
}
__device__ __forceinline__ ull pack2(float lo, float hi) {
    ull r;
    asm("mov.b64 %0, {%1, %2};" : "=l"(r) : "r"(__float_as_uint(lo)), "r"(__float_as_uint(hi)));
    return r;
}
__device__ __forceinline__ uint32_t smem_u32(const void* p) {
    uint32_t a;
    asm("{ .reg .u64 t; cvta.to.shared.u64 t, %1; cvt.u32.u64 %0, t; }" : "=r"(a) : "l"(p));
    return a;
}
__device__ __forceinline__ uint32_t sw128(uint32_t off) { return off ^ ((off >> 3) & 0x70); }
__device__ __forceinline__ void ldsm4(uint32_t* r, uint32_t addr) {
    asm volatile("ldmatrix.sync.aligned.m8n8.x4.shared.b16 {%0,%1,%2,%3}, [%4];"
                 : "=r"(r[0]), "=r"(r[1]), "=r"(r[2]), "=r"(r[3]) : "r"(addr));
}
__device__ __forceinline__ void mma16816(float* d, const uint32_t* a, uint32_t b0, uint32_t b1) {
    asm volatile(
        "mma.sync.aligned.m16n8k16.row.col.f32.bf16.bf16.f32 "
        "{%0,%1,%2,%3}, {%4,%5,%6,%7}, {%8,%9}, {%0,%1,%2,%3};"
        : "+f"(d[0]), "+f"(d[1]), "+f"(d[2]), "+f"(d[3])
        : "r"(a[0]), "r"(a[1]), "r"(a[2]), "r"(a[3]), "r"(b0), "r"(b1));
}
__device__ __forceinline__ uint32_t bf2x(float lo, float hi) {
    uint32_t r;
    asm("cvt.rn.bf16x2.f32 %0, %1, %2;" : "=r"(r) : "f"(hi), "f"(lo));
    return r;
}

// =====================================================================
// DCT operator M = C[:16]^T C[:16] and packed form
// =====================================================================
__global__ void k_dct() {
    int t = blockIdx.x, s = threadIdx.x;
    const double PI = 3.141592653589793238462643383279502884;
    double acc = 0.0;
    for (int kk = 0; kk < 16; kk++) {
        double scale = (kk == 0) ? sqrt(1.0 / 64.0) : sqrt(2.0 / 64.0);
        float ct = (float)(cos(PI * (t + 0.5) * kk / 64.0) * scale);
        float cs = (float)(cos(PI * (s + 0.5) * kk / 64.0) * scale);
        acc += (double)ct * (double)cs;
    }
    g_M[t * 64 + s] = (float)acc;
}
__global__ void k_pack() {
    int t2 = blockIdx.x, s = threadIdx.x;
    g_Mp[t2 * 64 + s] = pack2(g_M[(2 * t2) * 64 + s], g_M[(2 * t2 + 1) * 64 + s]);
}

// =====================================================================
// Merged weight split: all 7 weight tiles in one launch.
// =====================================================================
__global__ void k_wsplit_all(const float* __restrict__ Wq, const float* __restrict__ Wk,
                             const float* __restrict__ Wv, const float* __restrict__ Wo,
                             const float* __restrict__ W1, const float* __restrict__ W2) {
    int bi = blockIdx.x;
    int tile, ob;
    if (bi < 384) { tile = bi >> 6; ob = bi & 63; }
    else { tile = 6; ob = bi - 384; }
    const float* W; int ldw, col0, K;
    switch (tile) {
        case 0: W = Wq; ldw = 128; col0 = 0;   K = 128; break;
        case 1: W = Wk; ldw = 128; col0 = 0;   K = 128; break;
        case 2: W = Wv; ldw = 128; col0 = 0;   K = 128; break;
        case 3: W = Wo; ldw = 128; col0 = 0;   K = 128; break;
        case 4: W = W1; ldw = 256; col0 = 0;   K = 128; break;
        case 5: W = W1; ldw = 256; col0 = 128; K = 128; break;
        default: W = W2; ldw = 128; col0 = 0;  K = 256; break;
    }
    __nv_bfloat16* out = &g_wsp[tile][0];
    int idx = ob * 256 + threadIdx.x;
    int n = idx / K, k = idx - n * K;
    float w = W[(size_t)k * ldw + col0 + n];
    __nv_bfloat16 hi = __float2bfloat16(w);
    float r1 = __fsub_rn(w, __bfloat162float(hi));
    __nv_bfloat16 mid = __float2bfloat16(r1);
    float r2 = __fsub_rn(r1, __bfloat162float(mid));
    __nv_bfloat16 lo = __float2bfloat16(r2);
    out[(size_t)(0 * 128 + n) * K + k] = hi;
    out[(size_t)(1 * 128 + n) * K + k] = mid;
    out[(size_t)(2 * 128 + n) * K + k] = lo;
}

// =====================================================================
// Memory mix + temporal lowpass (FFMA2)
// =====================================================================
__global__ void __launch_bounds__(128) k_mix(const float* __restrict__ x,
                                             const float* __restrict__ mx) {
    __shared__ float s_p[64 * 128];
    __shared__ ull  s_Mp[32 * 64];
    const int bn = blockIdx.x;
    const int b = bn >> 6, n = bn & 63;
    const int tid = threadIdx.x;

    for (int i = tid; i < 2048; i += 128) s_Mp[i] = g_Mp[i];

    const float* xb = x + (size_t)(b * N_ + n) * D_;
    const float* mb = mx + ((size_t)(n * B_ + b) * T_) * D_;
    for (int i = tid; i < 8192; i += 128) {
        float mv = mb[i];
        float mv2 = __fadd_rn(__fmul_rn(0.05f, mv), __fmul_rn(0.95f, mv));
        s_p[i] = __fmul_rn(xb[(size_t)(i >> 7) * BND + (i & 127)], mv2);
    }
    __syncthreads();

    const int d = tid;
    ull acc[32];
#pragma unroll
    for (int t2 = 0; t2 < 32; t2++) acc[t2] = 0ull;
    for (int s = 0; s < 64; s++) {
        ull cp = dup2(s_p[s * 128 + d]);
#pragma unroll
        for (int t2 = 0; t2 < 32; t2++) ffma2(acc[t2], s_Mp[t2 * 64 + s], cp);
    }
    float* ob = g_mlp + (size_t)(b * N_ + n) * D_ + d;
#pragma unroll
    for (int t2 = 0; t2 < 32; t2++) {
        float2 f = *reinterpret_cast<float2*>(&acc[t2]);
        ob[(size_t)(2 * t2) * BND] = f.x;
        ob[(size_t)(2 * t2 + 1) * BND] = f.y;
    }
}

// =====================================================================
// Tensor-core GEMM (mma.sync bf16) + fused LIF, khalf-major, 2 CTAs/SM.
// smem: A splits 3x16KB + B splits 3x16KB = 97KB.
// =====================================================================
constexpr int OFF_A = 1024;
constexpr int OFF_B = 1024 + 3 * 16384;
constexpr int SGEMM = 1024 + 6 * 16384;   // 99328
constexpr int PPAD = 130;

template <int KCHUNKS, int MODE, int ASPLITS>
__global__ void __launch_bounds__(256, 2) k_mmag(
    const float* __restrict__ in, const __nv_bfloat16* __restrict__ wsp,
    float* __restrict__ out, int ldo, int ocol0, const float* __restrict__ gx) {
    extern __shared__ __align__(16) char smem_raw[];
    const uint32_t sbase = smem_u32(smem_raw);
    float* s_pre = (float*)(smem_raw + OFF_A);
    const int bn0 = blockIdx.x * 2;
    const int tid = threadIdx.x;
    const int wid = tid >> 5, lane = tid & 31;
    constexpr int KTOT = KCHUNKS * 128;

    const int m_base = (wid & 1) * 64;
    const int n_base = (wid >> 1) * 32;
    const int sub = lane >> 3, lr = lane & 7;
    const int arow_off = (sub & 1) * 8 + lr;
    const int akc = (sub >> 1) * 8;
    const int brow_off = (sub >> 1) * 8 + lr;
    const int bkc = (sub & 1) * 8;

    float acc[4][4][4];
#pragma unroll
    for (int i = 0; i < 4; i++)
#pragma unroll
        for (int j = 0; j < 4; j++)
#pragma unroll
            for (int e = 0; e < 4; e++) acc[i][j][e] = 0.f;

    for (int ch = 0; ch < KCHUNKS; ch++) {
        for (int kh = 0; kh < 2; kh++) {
            if (ch | kh) __syncthreads();
            // ---- B splits for this khalf: 3 tiles [128n][64k] bf16, SW128 ----
            for (int u = tid; u < 3072; u += 256) {
                int s = u >> 10;
                int r = u & 1023;
                int n = r >> 3, gsub = r & 7;
                const __nv_bfloat16* src =
                    wsp + ((size_t)(s * 128 + n) * KTOT + ch * 128 + kh * 64 + gsub * 8);
                uint4 val = *reinterpret_cast<const uint4*>(src);
                uint32_t off = sw128((n << 7) + (gsub << 4));
                *reinterpret_cast<uint4*>(smem_raw + OFF_B + s * 16384 + off) = val;
            }
            // ---- A for this khalf: load fp32, split to ASPLITS bf16 tiles ----
            for (int u = tid; u < 1024; u += 256) {
                int m = u >> 3, gsub = u & 7;
                int t = m & 63, tile = m >> 6;
                const float* src = in + (size_t)t * ((size_t)4096 * KTOT)
                                      + (size_t)(bn0 + tile) * KTOT + ch * 128 + kh * 64 + gsub * 8;
                float4 f0 = *reinterpret_cast<const float4*>(src);
                float4 f1 = *reinterpret_cast<const float4*>(src + 4);
                float a[8] = {f0.x, f0.y, f0.z, f0.w, f1.x, f1.y, f1.z, f1.w};
                __align__(16) __nv_bfloat16 hi[8], mid[8], lo[8];
#pragma unroll
                for (int e = 0; e < 8; e++) {
                    hi[e] = __float2bfloat16(a[e]);
                    if (ASPLITS >= 2) {
                        float r1 = __fsub_rn(a[e], __bfloat162float(hi[e]));
                        mid[e] = __float2bfloat16(r1);
                        if (ASPLITS >= 3) {
                            float r2 = __fsub_rn(r1, __bfloat162float(mid[e]));
                            lo[e] = __float2bfloat16(r2);
                        }
                    }
                }
                uint32_t off = sw128((m << 7) + (gsub << 4));
                *reinterpret_cast<uint4*>(smem_raw + OFF_A + 0 * 16384 + off) =
                    *reinterpret_cast<uint4*>(hi);
                if (ASPLITS >= 2)
                    *reinterpret_cast<uint4*>(smem_raw + OFF_A + 1 * 16384 + off) =
                        *reinterpret_cast<uint4*>(mid);
                if (ASPLITS >= 3)
                    *reinterpret_cast<uint4*>(smem_raw + OFF_A + 2 * 16384 + off) =
                        *reinterpret_cast<uint4*>(lo);
            }
            __syncthreads();

            const int NP = (ASPLITS == 3) ? 6 : (ASPLITS == 2 ? 5 : 3);
            const int PAs[6] = {0, 0, 1, 0, 1, 2};
            const int PBs[6] = {0, 1, 0, 2, 1, 0};
            const int PB1[6] = {0, 1, 2, 0, 0, 0};

            for (int p = 0; p < NP; p++) {
                int As = (ASPLITS == 1) ? 0 : PAs[p];
                int Bs = (ASPLITS == 1) ? PB1[p] : PBs[p];
                uint32_t Abase = sbase + OFF_A + As * 16384;
                uint32_t Bbase = sbase + OFF_B + Bs * 16384;
#pragma unroll
                for (int ks = 0; ks < 4; ks++) {
                    int k0 = ks * 16;
                    uint32_t afr[4][4];
#pragma unroll
                    for (int mf = 0; mf < 4; mf++)
                        ldsm4(afr[mf], Abase +
                              sw128(((m_base + mf * 16 + arow_off) << 7) + (k0 + akc) * 2));
                    uint32_t bfr[2][4];
#pragma unroll
                    for (int nf2 = 0; nf2 < 2; nf2++)
                        ldsm4(bfr[nf2], Bbase +
                              sw128(((n_base + nf2 * 16 + brow_off) << 7) + (k0 + bkc) * 2));
#pragma unroll
                    for (int mf = 0; mf < 4; mf++)
#pragma unroll
                        for (int nf = 0; nf < 4; nf++)
                            mma16816(acc[mf][nf], afr[mf],
                                     bfr[nf >> 1][(nf & 1) * 2], bfr[nf >> 1][(nf & 1) * 2 + 1]);
                }
            }
        }
    }
    __syncthreads();

    {
        const int qr = lane >> 2, qc = (lane & 3) * 2;
#pragma unroll
        for (int mf = 0; mf < 4; mf++)
#pragma unroll
            for (int nf = 0; nf < 4; nf++) {
                int row = m_base + mf * 16 + qr;
                int col = n_base + nf * 8 + qc;
                *reinterpret_cast<float2*>(&s_pre[row * PPAD + col]) =
                    make_float2(acc[mf][nf][0], acc[mf][nf][1]);
                *reinterpret_cast<float2*>(&s_pre[(row + 8) * PPAD + col]) =
                    make_float2(acc[mf][nf][2], acc[mf][nf][3]);
            }
    }
    __syncthreads();

    {
        const int tile = tid >> 7, c = tid & 127;
        const int bn = bn0 + tile;
        float vmem = 0.f;
        const size_t ostride = (size_t)4096 * ldo;
        const size_t obase = (size_t)bn * ldo + ocol0 + c;
        const size_t gbase = (size_t)bn * 128 + c;
#pragma unroll 1
        for (int t = 0; t < 64; t++) {
            float p = s_pre[(tile * 64 + t) * PPAD + c];
            vmem = __fadd_rn(vmem, __fmul_rn(__fsub_rn(p, vmem), 0.5f));
            float spk = (vmem >= 1.0f) ? 1.0f : 0.0f;
            if (vmem >= 1.0f) vmem = 0.0f;
            size_t oi = obase + (size_t)t * ostride;
            if (MODE == 0) {
                out[oi] = spk;
            } else {
                float g = gx[gbase + (size_t)t * (size_t)BND];
                out[oi] = __fmul_rn(g, __fsub_rn(1.0f, spk));
            }
        }
    }
}

// =====================================================================
// Attention via tensor cores (exact bf16): per (t,b) block.
// s_q/s_k: per head [64n][64k] bf16 SW128; s_vT: per head [64d][64m];
// s_attn: per head [64n][64m] (counts/8, exact bf16).
// =====================================================================
constexpr int ATT_Q = 0, ATT_K = 16384, ATT_V = 32768, ATT_AT = 49152;
constexpr int SATT = 65536;

__global__ void __launch_bounds__(256) k_attn3(const float* __restrict__ q,
                                               const float* __restrict__ k,
                                               const float* __restrict__ v,
                                               float* __restrict__ o) {
    extern __shared__ __align__(16) char sm_raw[];
    const uint32_t sbase = smem_u32(sm_raw);
    const size_t base = (size_t)blockIdx.x * 8192;
    const int tid = threadIdx.x;
    const int wid = tid >> 5, lane = tid & 31;

    // ---- load + convert to bf16 tiles ----
    for (int u = tid; u < 4096; u += 256) {
        int idx = u * 2;
        int n = idx >> 7, d = idx & 127;
        int h = d >> 6, dd = d & 63;
        float2 qv = *reinterpret_cast<const float2*>(&q[base + idx]);
        float2 kv = *reinterpret_cast<const float2*>(&k[base + idx]);
        float2 vv = *reinterpret_cast<const float2*>(&v[base + idx]);
        uint32_t qp = bf2x(qv.x, qv.y);
        uint32_t kp = bf2x(kv.x, kv.y);
        uint32_t off = sw128((n << 7) + (dd << 1));
        *reinterpret_cast<uint32_t*>(sm_raw + ATT_Q + h * 8192 + off) = qp;
        *reinterpret_cast<uint32_t*>(sm_raw + ATT_K + h * 8192 + off) = kp;
        // v transposed: rows = d, cols = m(=n)
        *reinterpret_cast<__nv_bfloat16*>(sm_raw + ATT_V + h * 8192 +
            sw128((dd << 7) + (n << 1))) = __float2bfloat16(vv.x);
        *reinterpret_cast<__nv_bfloat16*>(sm_raw + ATT_V + h * 8192 +
            sw128(((dd + 1) << 7) + (n << 1))) = __float2bfloat16(vv.y);
    }
    __syncthreads();

    const int sub = lane >> 3, lr = lane & 7;
    const int arow_off = (sub & 1) * 8 + lr;
    const int akc = (sub >> 1) * 8;
    const int brow_off = (sub >> 1) * 8 + lr;
    const int bkc = (sub & 1) * 8;
    const int qr = lane >> 2, qc = (lane & 3) * 2;

    float acc[8][4];

    // ---- phase 1: attn[h][n][m] = 0.125 * sum_k q k ----
    {
        const int h = wid & 1;
        const int n_b = (wid >> 1) * 16;
        uint32_t Abase = sbase + ATT_Q + h * 8192;
        uint32_t Bbase = sbase + ATT_K + h * 8192;
#pragma unroll
        for (int j = 0; j < 8; j++)
#pragma unroll
            for (int e = 0; e < 4; e++) acc[j][e] = 0.f;
#pragma unroll
        for (int ks = 0; ks < 4; ks++) {
            int k0 = ks * 16;
            uint32_t afr[4];
            ldsm4(afr, Abase + sw128(((n_b + arow_off) << 7) + (k0 + akc) * 2));
#pragma unroll
            for (int mf2 = 0; mf2 < 4; mf2++) {
                uint32_t bfr[4];
                ldsm4(bfr, Bbase + sw128(((mf2 * 16 + brow_off) << 7) + (k0 + bkc) * 2));
                mma16816(acc[mf2 * 2 + 0], afr, bfr[0], bfr[1]);
                mma16816(acc[mf2 * 2 + 1], afr, bfr[2], bfr[3]);
            }
        }
        // scale by 1/8 (exact) and store bf16 (exact: counts <= 64)
        uint32_t Obase = (uint32_t)(ATT_AT + h * 8192);
#pragma unroll
        for (int j = 0; j < 8; j++) {
            int m_col = j * 8 + qc;
            int r0 = n_b + qr;
            *reinterpret_cast<uint32_t*>(sm_raw + Obase +
                sw128((r0 << 7) + m_col * 2)) = bf2x(acc[j][0] * 0.125f, acc[j][1] * 0.125f);
            *reinterpret_cast<uint32_t*>(sm_raw + Obase +
                sw128(((r0 + 8) << 7) + m_col * 2)) = bf2x(acc[j][2] * 0.125f, acc[j][3] * 0.125f);
        }
    }
    __syncthreads();

    // ---- phase 2: o[n][h*64+d] = sum_m attn[h][n][m] * vT[h][d][m] ----
    {
        const int h = wid >> 2;
        const int n_b = (wid & 3) * 16;
        uint32_t Abase = sbase + ATT_AT + h * 8192;
        uint32_t Bbase = sbase + ATT_V + h * 8192;
#pragma unroll
        for (int j = 0; j < 8; j++)
#pragma unroll
            for (int e = 0; e < 4; e++) acc[j][e] = 0.f;
#pragma unroll
        for (int ks = 0; ks < 4; ks++) {
            int k0 = ks * 16;
            uint32_t afr[4];
            ldsm4(afr, Abase + sw128(((n_b + arow_off) << 7) + (k0 + akc) * 2));
#pragma unroll
            for (int df = 0; df < 4; df++) {
                uint32_t bfr[4];
                ldsm4(bfr, Bbase + sw128(((df * 16 + brow_off) << 7) + (k0 + bkc) * 2));
                mma16816(acc[df * 2 + 0], afr, bfr[0], bfr[1]);
                mma16816(acc[df * 2 + 1], afr, bfr[2], bfr[3]);
            }
        }
#pragma unroll
        for (int j = 0; j < 8; j++) {
            int d_col = h * 64 + j * 8 + qc;
            int r0 = n_b + qr;
            *reinterpret_cast<float2*>(&o[base + (size_t)r0 * 128 + d_col]) =
                make_float2(acc[j][0], acc[j][1]);
            *reinterpret_cast<float2*>(&o[base + (size_t)(r0 + 8) * 128 + d_col]) =
                make_float2(acc[j][2], acc[j][3]);
        }
    }
}

// =====================================================================
// Host side
// =====================================================================
extern "C" void kernel_launch(void* const* d_in, const int* in_sizes, int n_in,
                              void* d_out, int out_size) {
    const float* x  = (const float*)d_in[0];
    const float* mx = (const float*)d_in[1];
    const float* Wq = (const float*)d_in[2];
    const float* Wk = (const float*)d_in[3];
    const float* Wv = (const float*)d_in[4];
    const float* Wo = (const float*)d_in[5];
    const float* W1 = (const float*)d_in[6];
    const float* W2 = (const float*)d_in[7];
    float* out = (float*)d_out;

    void *p_mlp, *p_q, *p_k, *p_v, *p_o, *p_xg, *p_h1, *p_wsp;
    cudaGetSymbolAddress(&p_mlp, g_mlp);
    cudaGetSymbolAddress(&p_q, g_q);
    cudaGetSymbolAddress(&p_k, g_k);
    cudaGetSymbolAddress(&p_v, g_v);
    cudaGetSymbolAddress(&p_o, g_o);
    cudaGetSymbolAddress(&p_xg, g_xg);
    cudaGetSymbolAddress(&p_h1, g_h1);
    cudaGetSymbolAddress(&p_wsp, g_wsp);
    __nv_bfloat16* wsp = (__nv_bfloat16*)p_wsp;
    const size_t WSTRIDE = 3 * 128 * 256;

    cudaFuncSetAttribute(k_mmag<1, 0, 3>, cudaFuncAttributeMaxDynamicSharedMemorySize, SGEMM);
    cudaFuncSetAttribute(k_mmag<1, 1, 2>, cudaFuncAttributeMaxDynamicSharedMemorySize, SGEMM);
    cudaFuncSetAttribute(k_mmag<2, 1, 1>, cudaFuncAttributeMaxDynamicSharedMemorySize, SGEMM);
    cudaFuncSetAttribute(k_attn3, cudaFuncAttributeMaxDynamicSharedMemorySize, SATT);

    // launch order chosen so launch #6 (profiled) is the q GEMM
    k_dct<<<64, 64>>>();                                                   // 1
    k_pack<<<32, 64>>>();                                                  // 2
    k_wsplit_all<<<512, 256>>>(Wq, Wk, Wv, Wo, W1, W2);                    // 3
    k_mix<<<4096, 128>>>(x, mx);                                           // 4
    k_mmag<1, 0, 3><<<2048, 256, SGEMM>>>((const float*)p_mlp, wsp + 1 * WSTRIDE,
                                          (float*)p_k, 128, 0, nullptr);   // 5 (k)
    k_mmag<1, 0, 3><<<2048, 256, SGEMM>>>(x, wsp + 0 * WSTRIDE,
                                          (float*)p_q, 128, 0, nullptr);   // 6 (q) <- profiled
    k_mmag<1, 0, 3><<<2048, 256, SGEMM>>>((const float*)p_mlp, wsp + 2 * WSTRIDE,
                                          (float*)p_v, 128, 0, nullptr);   // 7 (v)
    k_attn3<<<4096, 256, SATT>>>((const float*)p_q, (const float*)p_k,
                                 (const float*)p_v, (float*)p_o);          // 8
    k_mmag<1, 1, 2><<<2048, 256, SGEMM>>>((const float*)p_o, wsp + 3 * WSTRIDE,
                                          (float*)p_xg, 128, 0, x);        // 9
    k_mmag<1, 0, 3><<<2048, 256, SGEMM>>>((const float*)p_xg, wsp + 4 * WSTRIDE,
                                          (float*)p_h1, 256, 0, nullptr);  // 10
    k_mmag<1, 0, 3><<<2048, 256, SGEMM>>>((const float*)p_xg, wsp + 5 * WSTRIDE,
                                          (float*)p_h1, 256, 128, nullptr);// 11
    k_mmag<2, 1, 1><<<2048, 256, SGEMM>>>((const float*)p_h1, wsp + 6 * WSTRIDE,
                                          out, 128, 0, (float*)p_xg);      // 12
}

// round 6
// speedup vs baseline: 2.3429x; 1.1117x over previous
#include <cuda_runtime.h>
#include <cuda_bf16.h>
#include <cstdint>

typedef unsigned long long ull;

constexpr int T_ = 64, B_ = 64, N_ = 64, D_ = 128, HID_ = 256;
constexpr int BND = B_ * N_ * D_;                      // 524288
constexpr size_t TOT  = (size_t)T_ * BND;              // 33554432
constexpr size_t TOTH = (size_t)T_ * B_ * N_ * HID_;   // 67108864

// -------- scratch (no allocations allowed) --------
__device__ float g_M[64 * 64];
__device__ ull   g_Mp[32 * 64];
__device__ __nv_bfloat16 g_xs[3][TOT];    // x splits
__device__ __nv_bfloat16 g_ms[3][TOT];    // mlp splits
__device__ __nv_bfloat16 g_os[2][TOT];    // o splits (exact)
__device__ __nv_bfloat16 g_xgs[3][TOT];   // xg splits
__device__ float         g_xg[TOT];       // xg fp32 (for final gating)
__device__ __nv_bfloat16 g_q[TOT];        // binary spikes, bf16 exact
__device__ __nv_bfloat16 g_k[TOT];
__device__ __nv_bfloat16 g_v[TOT];
__device__ __nv_bfloat16 g_h1[TOTH];
__device__ __nv_bfloat16 g_wsp[7][3 * 128 * 256];

// -------- helpers --------
__device__ __forceinline__ void ffma2(ull& d, ull a, ull b) {
    asm("fma.rn.f32x2 %0, %1, %2, %0;" : "+l"(d) : "l"(a), "l"(b));
}
__device__ __forceinline__ ull dup2(float x) {
    ull r; unsigned u = __float_as_uint(x);
    asm("mov.b64 %0, {%1, %1};" : "=l"(r) : "r"(u));
    return r;
}
__device__ __forceinline__ ull pack2(float lo, float hi) {
    ull r;
    asm("mov.b64 %0, {%1, %2};" : "=l"(r) : "r"(__float_as_uint(lo)), "r"(__float_as_uint(hi)));
    return r;
}
__device__ __forceinline__ uint32_t smem_u32(const void* p) {
    uint32_t a;
    asm("{ .reg .u64 t; cvta.to.shared.u64 t, %1; cvt.u32.u64 %0, t; }" : "=r"(a) : "l"(p));
    return a;
}
__device__ __forceinline__ uint32_t sw128(uint32_t off) { return off ^ ((off >> 3) & 0x70); }
__device__ __forceinline__ void ldsm4(uint32_t* r, uint32_t addr) {
    asm volatile("ldmatrix.sync.aligned.m8n8.x4.shared.b16 {%0,%1,%2,%3}, [%4];"
                 : "=r"(r[0]), "=r"(r[1]), "=r"(r[2]), "=r"(r[3]) : "r"(addr));
}
__device__ __forceinline__ void mma16816(float* d, const uint32_t* a, uint32_t b0, uint32_t b1) {
    asm volatile(
        "mma.sync.aligned.m16n8k16.row.col.f32.bf16.bf16.f32 "
        "{%0,%1,%2,%3}, {%4,%5,%6,%7}, {%8,%9}, {%0,%1,%2,%3};"
        : "+f"(d[0]), "+f"(d[1]), "+f"(d[2]), "+f"(d[3])
        : "r"(a[0]), "r"(a[1]), "r"(a[2]), "r"(a[3]), "r"(b0), "r"(b1));
}
__device__ __forceinline__ uint32_t bf2x(float lo, float hi) {
    uint32_t r;
    asm("cvt.rn.bf16x2.f32 %0, %1, %2;" : "=r"(r) : "f"(hi), "f"(lo));
    return r;
}
__device__ __forceinline__ void cpa16(uint32_t dst, const void* src) {
    asm volatile("cp.async.cg.shared.global [%0], [%1], 16;" :: "r"(dst), "l"(src));
}
__device__ __forceinline__ void cpa_commit_wait() {
    asm volatile("cp.async.commit_group;");
    asm volatile("cp.async.wait_group 0;");
}

// =====================================================================
// DCT operator M = C[:16]^T C[:16] and packed form
// =====================================================================
__global__ void k_dct() {
    int t = blockIdx.x, s = threadIdx.x;
    const double PI = 3.141592653589793238462643383279502884;
    double acc = 0.0;
    for (int kk = 0; kk < 16; kk++) {
        double scale = (kk == 0) ? sqrt(1.0 / 64.0) : sqrt(2.0 / 64.0);
        float ct = (float)(cos(PI * (t + 0.5) * kk / 64.0) * scale);
        float cs = (float)(cos(PI * (s + 0.5) * kk / 64.0) * scale);
        acc += (double)ct * (double)cs;
    }
    g_M[t * 64 + s] = (float)acc;
}
__global__ void k_pack() {
    int t2 = blockIdx.x, s = threadIdx.x;
    g_Mp[t2 * 64 + s] = pack2(g_M[(2 * t2) * 64 + s], g_M[(2 * t2 + 1) * 64 + s]);
}

// =====================================================================
// Merged weight split: all 7 weight tiles in one launch.
// =====================================================================
__global__ void k_wsplit_all(const float* __restrict__ Wq, const float* __restrict__ Wk,
                             const float* __restrict__ Wv, const float* __restrict__ Wo,
                             const float* __restrict__ W1, const float* __restrict__ W2) {
    int bi = blockIdx.x;
    int tile, ob;
    if (bi < 384) { tile = bi >> 6; ob = bi & 63; }
    else { tile = 6; ob = bi - 384; }
    const float* W; int ldw, col0, K;
    switch (tile) {
        case 0: W = Wq; ldw = 128; col0 = 0;   K = 128; break;
        case 1: W = Wk; ldw = 128; col0 = 0;   K = 128; break;
        case 2: W = Wv; ldw = 128; col0 = 0;   K = 128; break;
        case 3: W = Wo; ldw = 128; col0 = 0;   K = 128; break;
        case 4: W = W1; ldw = 256; col0 = 0;   K = 128; break;
        case 5: W = W1; ldw = 256; col0 = 128; K = 128; break;
        default: W = W2; ldw = 128; col0 = 0;  K = 256; break;
    }
    __nv_bfloat16* out = &g_wsp[tile][0];
    int idx = ob * 256 + threadIdx.x;
    int n = idx / K, k = idx - n * K;
    float w = W[(size_t)k * ldw + col0 + n];
    __nv_bfloat16 hi = __float2bfloat16(w);
    float r1 = __fsub_rn(w, __bfloat162float(hi));
    __nv_bfloat16 mid = __float2bfloat16(r1);
    float r2 = __fsub_rn(r1, __bfloat162float(mid));
    __nv_bfloat16 lo = __float2bfloat16(r2);
    out[(size_t)(0 * 128 + n) * K + k] = hi;
    out[(size_t)(1 * 128 + n) * K + k] = mid;
    out[(size_t)(2 * 128 + n) * K + k] = lo;
}

// =====================================================================
// Memory mix + temporal lowpass; emits x splits and mlp splits (bf16).
// =====================================================================
__global__ void __launch_bounds__(128) k_mix(const float* __restrict__ x,
                                             const float* __restrict__ mx) {
    __shared__ float s_p[64 * 128];
    __shared__ ull  s_Mp[32 * 64];
    const int bn = blockIdx.x;
    const int b = bn >> 6, n = bn & 63;
    const int tid = threadIdx.x;

    for (int i = tid; i < 2048; i += 128) s_Mp[i] = g_Mp[i];

    const float* xb = x + (size_t)(b * N_ + n) * D_;
    const float* mb = mx + ((size_t)(n * B_ + b) * T_) * D_;
    for (int i = tid; i < 8192; i += 128) {
        int s = i >> 7, d = i & 127;
        float mv = mb[i];
        float mv2 = __fadd_rn(__fmul_rn(0.05f, mv), __fmul_rn(0.95f, mv));
        float xv = xb[(size_t)s * BND + d];
        // x splits
        {
            size_t oi = ((size_t)s * 4096 + bn) * 128 + d;
            __nv_bfloat16 hi = __float2bfloat16(xv);
            float r1 = __fsub_rn(xv, __bfloat162float(hi));
            __nv_bfloat16 mid = __float2bfloat16(r1);
            float r2 = __fsub_rn(r1, __bfloat162float(mid));
            g_xs[0][oi] = hi;
            g_xs[1][oi] = mid;
            g_xs[2][oi] = __float2bfloat16(r2);
        }
        s_p[i] = __fmul_rn(xv, mv2);
    }
    __syncthreads();

    const int d = tid;
    ull acc[32];
#pragma unroll
    for (int t2 = 0; t2 < 32; t2++) acc[t2] = 0ull;
    for (int s = 0; s < 64; s++) {
        ull cp = dup2(s_p[s * 128 + d]);
#pragma unroll
        for (int t2 = 0; t2 < 32; t2++) ffma2(acc[t2], s_Mp[t2 * 64 + s], cp);
    }
#pragma unroll
    for (int t2 = 0; t2 < 32; t2++) {
        float2 f = *reinterpret_cast<float2*>(&acc[t2]);
#pragma unroll
        for (int e = 0; e < 2; e++) {
            float v = (e == 0) ? f.x : f.y;
            size_t oi = ((size_t)(2 * t2 + e) * 4096 + bn) * 128 + d;
            __nv_bfloat16 hi = __float2bfloat16(v);
            float r1 = __fsub_rn(v, __bfloat162float(hi));
            __nv_bfloat16 mid = __float2bfloat16(r1);
            float r2 = __fsub_rn(r1, __bfloat162float(mid));
            g_ms[0][oi] = hi;
            g_ms[1][oi] = mid;
            g_ms[2][oi] = __float2bfloat16(r2);
        }
    }
}

// =====================================================================
// Tensor-core GEMM (mma.sync bf16) + fused LIF. cp.async pre-split A.
// Per CTA: 2 bn tiles (M=128) x N=128. smem 97KB -> 2 CTAs/SM.
// MODE 0: spike (bf16). MODE 1: xg fp32 + 3 splits. MODE 2: final fp32.
// =====================================================================
constexpr int OFF_A = 1024;
constexpr int OFF_B = 1024 + 3 * 16384;
constexpr int SGEMM = 1024 + 6 * 16384;   // 99328
constexpr int PPAD = 130;

template <int KCHUNKS, int MODE, int NSPLITS>
__global__ void __launch_bounds__(256, 2) k_mmag(
    const __nv_bfloat16* __restrict__ aspl, size_t asstride,
    const __nv_bfloat16* __restrict__ wsp,
    void* __restrict__ outp, int ldo, int ocol0,
    const float* __restrict__ gx,
    __nv_bfloat16* __restrict__ so0, __nv_bfloat16* __restrict__ so1,
    __nv_bfloat16* __restrict__ so2) {
    extern __shared__ __align__(16) char smem_raw[];
    const uint32_t sbase = smem_u32(smem_raw);
    float* s_pre = (float*)(smem_raw + 1024);
    const int bn0 = blockIdx.x * 2;
    const int tid = threadIdx.x;
    const int wid = tid >> 5, lane = tid & 31;
    constexpr int KTOT = KCHUNKS * 128;

    const int m_base = (wid & 1) * 64;
    const int n_base = (wid >> 1) * 32;
    const int sub = lane >> 3, lr = lane & 7;
    const int arow_off = (sub & 1) * 8 + lr;
    const int akc = (sub >> 1) * 8;
    const int brow_off = (sub >> 1) * 8 + lr;
    const int bkc = (sub & 1) * 8;

    float acc[4][4][4];
#pragma unroll
    for (int i = 0; i < 4; i++)
#pragma unroll
        for (int j = 0; j < 4; j++)
#pragma unroll
            for (int e = 0; e < 4; e++) acc[i][j][e] = 0.f;

    for (int ch = 0; ch < KCHUNKS; ch++) {
        for (int kh = 0; kh < 2; kh++) {
            if (ch | kh) __syncthreads();
            // ---- B splits via cp.async (3 tiles [128n][64k] bf16, SW128) ----
            for (int u = tid; u < 3072; u += 256) {
                int s = u >> 10, r = u & 1023, n = r >> 3, g = r & 7;
                const __nv_bfloat16* src =
                    wsp + ((size_t)(s * 128 + n) * KTOT + ch * 128 + kh * 64 + g * 8);
                cpa16(sbase + OFF_B + s * 16384 + sw128((n << 7) + (g << 4)), src);
            }
            // ---- A splits via cp.async ----
            for (int u = tid; u < NSPLITS * 1024; u += 256) {
                int s = u >> 10, r = u & 1023, m = r >> 3, g = r & 7;
                int t = m & 63, tile = m >> 6;
                const __nv_bfloat16* src = aspl + (size_t)s * asstride +
                    ((size_t)t * 4096 + bn0 + tile) * KTOT + ch * 128 + kh * 64 + g * 8;
                cpa16(sbase + OFF_A + s * 16384 + sw128((m << 7) + (g << 4)), src);
            }
            cpa_commit_wait();
            __syncthreads();

            const int NP = (NSPLITS == 3) ? 6 : (NSPLITS == 2 ? 5 : 3);
            const int PAs[6] = {0, 0, 1, 0, 1, 2};
            const int PBs[6] = {0, 1, 0, 2, 1, 0};
            const int PB1[6] = {0, 1, 2, 0, 0, 0};

            for (int p = 0; p < NP; p++) {
                int As = (NSPLITS == 1) ? 0 : PAs[p];
                int Bs = (NSPLITS == 1) ? PB1[p] : PBs[p];
                uint32_t Abase = sbase + OFF_A + As * 16384;
                uint32_t Bbase = sbase + OFF_B + Bs * 16384;
#pragma unroll
                for (int ks = 0; ks < 4; ks++) {
                    int k0 = ks * 16;
                    uint32_t afr[4][4];
#pragma unroll
                    for (int mf = 0; mf < 4; mf++)
                        ldsm4(afr[mf], Abase +
                              sw128(((m_base + mf * 16 + arow_off) << 7) + (k0 + akc) * 2));
                    uint32_t bfr[2][4];
#pragma unroll
                    for (int nf2 = 0; nf2 < 2; nf2++)
                        ldsm4(bfr[nf2], Bbase +
                              sw128(((n_base + nf2 * 16 + brow_off) << 7) + (k0 + bkc) * 2));
#pragma unroll
                    for (int mf = 0; mf < 4; mf++)
#pragma unroll
                        for (int nf = 0; nf < 4; nf++)
                            mma16816(acc[mf][nf], afr[mf],
                                     bfr[nf >> 1][(nf & 1) * 2], bfr[nf >> 1][(nf & 1) * 2 + 1]);
                }
            }
        }
    }
    __syncthreads();

    {
        const int qr = lane >> 2, qc = (lane & 3) * 2;
#pragma unroll
        for (int mf = 0; mf < 4; mf++)
#pragma unroll
            for (int nf = 0; nf < 4; nf++) {
                int row = m_base + mf * 16 + qr;
                int col = n_base + nf * 8 + qc;
                *reinterpret_cast<float2*>(&s_pre[row * PPAD + col]) =
                    make_float2(acc[mf][nf][0], acc[mf][nf][1]);
                *reinterpret_cast<float2*>(&s_pre[(row + 8) * PPAD + col]) =
                    make_float2(acc[mf][nf][2], acc[mf][nf][3]);
            }
    }
    __syncthreads();

    // ---- fused LIF scan ----
    {
        const int tile = tid >> 7, c = tid & 127;
        const int bn = bn0 + tile;
        float vmem = 0.f;
        const size_t ostride = (size_t)4096 * ldo;
        const size_t obase = (size_t)bn * ldo + ocol0 + c;
        const size_t gbase = (size_t)bn * 128 + c;
#pragma unroll 1
        for (int t = 0; t < 64; t++) {
            float p = s_pre[(tile * 64 + t) * PPAD + c];
            vmem = __fadd_rn(vmem, __fmul_rn(__fsub_rn(p, vmem), 0.5f));
            float spk = (vmem >= 1.0f) ? 1.0f : 0.0f;
            if (vmem >= 1.0f) vmem = 0.0f;
            size_t oi = obase + (size_t)t * ostride;
            if (MODE == 0) {
                ((__nv_bfloat16*)outp)[oi] = __float2bfloat16(spk);
            } else {
                float g = gx[gbase + (size_t)t * (size_t)BND];
                float val = __fmul_rn(g, __fsub_rn(1.0f, spk));
                ((float*)outp)[oi] = val;
                if (MODE == 1) {
                    __nv_bfloat16 hi = __float2bfloat16(val);
                    float r1 = __fsub_rn(val, __bfloat162float(hi));
                    __nv_bfloat16 mid = __float2bfloat16(r1);
                    float r2 = __fsub_rn(r1, __bfloat162float(mid));
                    so0[oi] = hi;
                    so1[oi] = mid;
                    so2[oi] = __float2bfloat16(r2);
                }
            }
        }
    }
}

// =====================================================================
// Attention via tensor cores (exact bf16 in/out), emits o splits.
// =====================================================================
constexpr int ATT_Q = 0, ATT_K = 16384, ATT_V = 32768, ATT_AT = 49152;
constexpr int SATT = 65536;

__global__ void __launch_bounds__(256) k_attn3(const __nv_bfloat16* __restrict__ q,
                                               const __nv_bfloat16* __restrict__ k,
                                               const __nv_bfloat16* __restrict__ v,
                                               __nv_bfloat16* __restrict__ so0,
                                               __nv_bfloat16* __restrict__ so1) {
    extern __shared__ __align__(16) char sm_raw[];
    const uint32_t sbase = smem_u32(sm_raw);
    const size_t base = (size_t)blockIdx.x * 8192;
    const int tid = threadIdx.x;
    const int wid = tid >> 5, lane = tid & 31;

    // ---- load bf16 tiles ----
    for (int u = tid; u < 4096; u += 256) {
        int n = u >> 6;
        int d = (u & 63) * 2;
        int h = d >> 6, dd = d & 63;
        uint32_t qp = *reinterpret_cast<const uint32_t*>(&q[base + 2 * u]);
        uint32_t kp = *reinterpret_cast<const uint32_t*>(&k[base + 2 * u]);
        uint32_t vp = *reinterpret_cast<const uint32_t*>(&v[base + 2 * u]);
        uint32_t off = sw128((n << 7) + (dd << 1));
        *reinterpret_cast<uint32_t*>(sm_raw + ATT_Q + h * 8192 + off) = qp;
        *reinterpret_cast<uint32_t*>(sm_raw + ATT_K + h * 8192 + off) = kp;
        // v transposed: rows = d, cols = m(=n)
        *reinterpret_cast<uint16_t*>(sm_raw + ATT_V + h * 8192 +
            sw128((dd << 7) + (n << 1))) = (uint16_t)(vp & 0xffffu);
        *reinterpret_cast<uint16_t*>(sm_raw + ATT_V + h * 8192 +
            sw128(((dd + 1) << 7) + (n << 1))) = (uint16_t)(vp >> 16);
    }
    __syncthreads();

    const int sub = lane >> 3, lr = lane & 7;
    const int arow_off = (sub & 1) * 8 + lr;
    const int akc = (sub >> 1) * 8;
    const int brow_off = (sub >> 1) * 8 + lr;
    const int bkc = (sub & 1) * 8;
    const int qr = lane >> 2, qc = (lane & 3) * 2;

    float acc[8][4];

    // ---- phase 1: attn[h][n][m] = 0.125 * q·k ----
    {
        const int h = wid & 1;
        const int n_b = (wid >> 1) * 16;
        uint32_t Abase = sbase + ATT_Q + h * 8192;
        uint32_t Bbase = sbase + ATT_K + h * 8192;
#pragma unroll
        for (int j = 0; j < 8; j++)
#pragma unroll
            for (int e = 0; e < 4; e++) acc[j][e] = 0.f;
#pragma unroll
        for (int ks = 0; ks < 4; ks++) {
            int k0 = ks * 16;
            uint32_t afr[4];
            ldsm4(afr, Abase + sw128(((n_b + arow_off) << 7) + (k0 + akc) * 2));
#pragma unroll
            for (int mf2 = 0; mf2 < 4; mf2++) {
                uint32_t bfr[4];
                ldsm4(bfr, Bbase + sw128(((mf2 * 16 + brow_off) << 7) + (k0 + bkc) * 2));
                mma16816(acc[mf2 * 2 + 0], afr, bfr[0], bfr[1]);
                mma16816(acc[mf2 * 2 + 1], afr, bfr[2], bfr[3]);
            }
        }
        uint32_t Obase = (uint32_t)(ATT_AT + h * 8192);
#pragma unroll
        for (int j = 0; j < 8; j++) {
            int m_col = j * 8 + qc;
            int r0 = n_b + qr;
            *reinterpret_cast<uint32_t*>(sm_raw + Obase +
                sw128((r0 << 7) + m_col * 2)) = bf2x(acc[j][0] * 0.125f, acc[j][1] * 0.125f);
            *reinterpret_cast<uint32_t*>(sm_raw + Obase +
                sw128(((r0 + 8) << 7) + m_col * 2)) = bf2x(acc[j][2] * 0.125f, acc[j][3] * 0.125f);
        }
    }
    __syncthreads();

    // ---- phase 2: o[n][h*64+d] = attn · vT, emit exact 2-way splits ----
    {
        const int h = wid >> 2;
        const int n_b = (wid & 3) * 16;
        uint32_t Abase = sbase + ATT_AT + h * 8192;
        uint32_t Bbase = sbase + ATT_V + h * 8192;
#pragma unroll
        for (int j = 0; j < 8; j++)
#pragma unroll
            for (int e = 0; e < 4; e++) acc[j][e] = 0.f;
#pragma unroll
        for (int ks = 0; ks < 4; ks++) {
            int k0 = ks * 16;
            uint32_t afr[4];
            ldsm4(afr, Abase + sw128(((n_b + arow_off) << 7) + (k0 + akc) * 2));
#pragma unroll
            for (int df = 0; df < 4; df++) {
                uint32_t bfr[4];
                ldsm4(bfr, Bbase + sw128(((df * 16 + brow_off) << 7) + (k0 + bkc) * 2));
                mma16816(acc[df * 2 + 0], afr, bfr[0], bfr[1]);
                mma16816(acc[df * 2 + 1], afr, bfr[2], bfr[3]);
            }
        }
#pragma unroll
        for (int j = 0; j < 8; j++) {
            int d_col = h * 64 + j * 8 + qc;
#pragma unroll
            for (int half = 0; half < 2; half++) {
                int r0 = n_b + qr + half * 8;
                float f0 = acc[j][half * 2 + 0], f1 = acc[j][half * 2 + 1];
                float h0 = __bfloat162float(__float2bfloat16(f0));
                float h1v = __bfloat162float(__float2bfloat16(f1));
                size_t oi = base + (size_t)r0 * 128 + d_col;
                *reinterpret_cast<uint32_t*>(&so0[oi]) = bf2x(f0, f1);
                *reinterpret_cast<uint32_t*>(&so1[oi]) =
                    bf2x(__fsub_rn(f0, h0), __fsub_rn(f1, h1v));
            }
        }
    }
}

// =====================================================================
// Host side
// =====================================================================
extern "C" void kernel_launch(void* const* d_in, const int* in_sizes, int n_in,
                              void* d_out, int out_size) {
    const float* x  = (const float*)d_in[0];
    const float* mx = (const float*)d_in[1];
    const float* Wq = (const float*)d_in[2];
    const float* Wk = (const float*)d_in[3];
    const float* Wv = (const float*)d_in[4];
    const float* Wo = (const float*)d_in[5];
    const float* W1 = (const float*)d_in[6];
    const float* W2 = (const float*)d_in[7];
    float* out = (float*)d_out;

    void *p_xs, *p_ms, *p_os, *p_xgs, *p_xg, *p_q, *p_k, *p_v, *p_h1, *p_wsp;
    cudaGetSymbolAddress(&p_xs, g_xs);
    cudaGetSymbolAddress(&p_ms, g_ms);
    cudaGetSymbolAddress(&p_os, g_os);
    cudaGetSymbolAddress(&p_xgs, g_xgs);
    cudaGetSymbolAddress(&p_xg, g_xg);
    cudaGetSymbolAddress(&p_q, g_q);
    cudaGetSymbolAddress(&p_k, g_k);
    cudaGetSymbolAddress(&p_v, g_v);
    cudaGetSymbolAddress(&p_h1, g_h1);
    cudaGetSymbolAddress(&p_wsp, g_wsp);
    __nv_bfloat16* xs = (__nv_bfloat16*)p_xs;
    __nv_bfloat16* ms = (__nv_bfloat16*)p_ms;
    __nv_bfloat16* os = (__nv_bfloat16*)p_os;
    __nv_bfloat16* xgs = (__nv_bfloat16*)p_xgs;
    __nv_bfloat16* wsp = (__nv_bfloat16*)p_wsp;
    const size_t WSTRIDE = 3 * 128 * 256;

    cudaFuncSetAttribute(k_mmag<1, 0, 3>, cudaFuncAttributeMaxDynamicSharedMemorySize, SGEMM);
    cudaFuncSetAttribute(k_mmag<1, 1, 2>, cudaFuncAttributeMaxDynamicSharedMemorySize, SGEMM);
    cudaFuncSetAttribute(k_mmag<2, 2, 1>, cudaFuncAttributeMaxDynamicSharedMemorySize, SGEMM);
    cudaFuncSetAttribute(k_attn3, cudaFuncAttributeMaxDynamicSharedMemorySize, SATT);

    k_dct<<<64, 64>>>();                                                    // 1
    k_pack<<<32, 64>>>();                                                   // 2
    k_wsplit_all<<<512, 256>>>(Wq, Wk, Wv, Wo, W1, W2);                     // 3
    k_mix<<<4096, 128>>>(x, mx);                                            // 4
    // q = LIF(x @ Wq)  (pre-split x)
    k_mmag<1, 0, 3><<<2048, 256, SGEMM>>>(xs, TOT, wsp + 0 * WSTRIDE,
        p_q, 128, 0, nullptr, nullptr, nullptr, nullptr);                   // 5
    k_mmag<1, 0, 3><<<2048, 256, SGEMM>>>(ms, TOT, wsp + 1 * WSTRIDE,
        p_k, 128, 0, nullptr, nullptr, nullptr, nullptr);                   // 6
    k_mmag<1, 0, 3><<<2048, 256, SGEMM>>>(ms, TOT, wsp + 2 * WSTRIDE,
        p_v, 128, 0, nullptr, nullptr, nullptr, nullptr);                   // 7
    k_attn3<<<4096, 256, SATT>>>((const __nv_bfloat16*)p_q, (const __nv_bfloat16*)p_k,
        (const __nv_bfloat16*)p_v, os, os + TOT);                           // 8
    // xg = x * (1 - LIF(o @ Wo)); emit xg fp32 + splits
    k_mmag<1, 1, 2><<<2048, 256, SGEMM>>>(os, TOT, wsp + 3 * WSTRIDE,
        p_xg, 128, 0, x, xgs, xgs + TOT, xgs + 2 * TOT);                    // 9
    // h1 = LIF(xg @ W1) (bf16 spikes, two N-halves)
    k_mmag<1, 0, 3><<<2048, 256, SGEMM>>>(xgs, TOT, wsp + 4 * WSTRIDE,
        p_h1, 256, 0, nullptr, nullptr, nullptr, nullptr);                  // 10
    k_mmag<1, 0, 3><<<2048, 256, SGEMM>>>(xgs, TOT, wsp + 5 * WSTRIDE,
        p_h1, 256, 128, nullptr, nullptr, nullptr, nullptr);                // 11
    // out = xg * (1 - LIF(h1 @ W2))  (binary h1, 1 split, K=256)
    k_mmag<2, 2, 1><<<2048, 256, SGEMM>>>((const __nv_bfloat16*)p_h1, 0,
        wsp + 6 * WSTRIDE, out, 128, 0, (const float*)p_xg,
        nullptr, nullptr, nullptr);                                         // 12
}

// round 7
// speedup vs baseline: 2.6133x; 1.1154x over previous
#include <cuda_runtime.h>
#include <cuda_bf16.h>
#include <cstdint>

typedef unsigned long long ull;

constexpr int T_ = 64, B_ = 64, N_ = 64, D_ = 128, HID_ = 256;
constexpr int BND = B_ * N_ * D_;                      // 524288
constexpr size_t TOT  = (size_t)T_ * BND;              // 33554432
constexpr size_t TOTH = (size_t)T_ * B_ * N_ * HID_;   // 67108864

// -------- scratch (no allocations allowed) --------
__device__ float g_M[64 * 64];
__device__ ull   g_Mp[32 * 64];
__device__ __nv_bfloat16 g_xs[3][TOT];    // x splits
__device__ __nv_bfloat16 g_ms[3][TOT];    // mlp splits
__device__ __nv_bfloat16 g_os[2][TOT];    // o splits (exact)
__device__ __nv_bfloat16 g_xgs[3][TOT];   // xg splits
__device__ float         g_xg[TOT];       // xg fp32 (for final gating)
__device__ __nv_bfloat16 g_q[TOT];
__device__ __nv_bfloat16 g_k[TOT];
__device__ __nv_bfloat16 g_v[TOT];
__device__ __nv_bfloat16 g_h1[TOTH];
__device__ __nv_bfloat16 g_wsp[7][3 * 128 * 256];

// -------- helpers --------
__device__ __forceinline__ void ffma2(ull& d, ull a, ull b) {
    asm("fma.rn.f32x2 %0, %1, %2, %0;" : "+l"(d) : "l"(a), "l"(b));
}
__device__ __forceinline__ ull dup2(float x) {
    ull r; unsigned u = __float_as_uint(x);
    asm("mov.b64 %0, {%1, %1};" : "=l"(r) : "r"(u));
    return r;
}
__device__ __forceinline__ ull pack2(float lo, float hi) {
    ull r;
    asm("mov.b64 %0, {%1, %2};" : "=l"(r) : "r"(__float_as_uint(lo)), "r"(__float_as_uint(hi)));
    return r;
}
__device__ __forceinline__ uint32_t smem_u32(const void* p) {
    uint32_t a;
    asm("{ .reg .u64 t; cvta.to.shared.u64 t, %1; cvt.u32.u64 %0, t; }" : "=r"(a) : "l"(p));
    return a;
}
__device__ __forceinline__ uint32_t sw128(uint32_t off) { return off ^ ((off >> 3) & 0x70); }
__device__ __forceinline__ void ldsm4(uint32_t* r, uint32_t addr) {
    asm volatile("ldmatrix.sync.aligned.m8n8.x4.shared.b16 {%0,%1,%2,%3}, [%4];"
                 : "=r"(r[0]), "=r"(r[1]), "=r"(r[2]), "=r"(r[3]) : "r"(addr));
}
__device__ __forceinline__ void mma16816(float* d, const uint32_t* a, uint32_t b0, uint32_t b1) {
    asm volatile(
        "mma.sync.aligned.m16n8k16.row.col.f32.bf16.bf16.f32 "
        "{%0,%1,%2,%3}, {%4,%5,%6,%7}, {%8,%9}, {%0,%1,%2,%3};"
        : "+f"(d[0]), "+f"(d[1]), "+f"(d[2]), "+f"(d[3])
        : "r"(a[0]), "r"(a[1]), "r"(a[2]), "r"(a[3]), "r"(b0), "r"(b1));
}
__device__ __forceinline__ uint32_t bf2x(float lo, float hi) {
    uint32_t r;
    asm("cvt.rn.bf16x2.f32 %0, %1, %2;" : "=r"(r) : "f"(hi), "f"(lo));
    return r;
}
__device__ __forceinline__ void cpa16(uint32_t dst, const void* src) {
    asm volatile("cp.async.cg.shared.global [%0], [%1], 16;" :: "r"(dst), "l"(src));
}
__device__ __forceinline__ void cpa_commit() {
    asm volatile("cp.async.commit_group;");
}
template <int NWAIT>
__device__ __forceinline__ void cpa_wait() {
    asm volatile("cp.async.wait_group %0;" :: "n"(NWAIT));
}

// =====================================================================
// DCT operator + packed form
// =====================================================================
__global__ void k_dct() {
    int t = blockIdx.x, s = threadIdx.x;
    const double PI = 3.141592653589793238462643383279502884;
    double acc = 0.0;
    for (int kk = 0; kk < 16; kk++) {
        double scale = (kk == 0) ? sqrt(1.0 / 64.0) : sqrt(2.0 / 64.0);
        float ct = (float)(cos(PI * (t + 0.5) * kk / 64.0) * scale);
        float cs = (float)(cos(PI * (s + 0.5) * kk / 64.0) * scale);
        acc += (double)ct * (double)cs;
    }
    g_M[t * 64 + s] = (float)acc;
}
__global__ void k_pack() {
    int t2 = blockIdx.x, s = threadIdx.x;
    g_Mp[t2 * 64 + s] = pack2(g_M[(2 * t2) * 64 + s], g_M[(2 * t2 + 1) * 64 + s]);
}

// =====================================================================
// Merged weight split
// =====================================================================
__global__ void k_wsplit_all(const float* __restrict__ Wq, const float* __restrict__ Wk,
                             const float* __restrict__ Wv, const float* __restrict__ Wo,
                             const float* __restrict__ W1, const float* __restrict__ W2) {
    int bi = blockIdx.x;
    int tile, ob;
    if (bi < 384) { tile = bi >> 6; ob = bi & 63; }
    else { tile = 6; ob = bi - 384; }
    const float* W; int ldw, col0, K;
    switch (tile) {
        case 0: W = Wq; ldw = 128; col0 = 0;   K = 128; break;
        case 1: W = Wk; ldw = 128; col0 = 0;   K = 128; break;
        case 2: W = Wv; ldw = 128; col0 = 0;   K = 128; break;
        case 3: W = Wo; ldw = 128; col0 = 0;   K = 128; break;
        case 4: W = W1; ldw = 256; col0 = 0;   K = 128; break;
        case 5: W = W1; ldw = 256; col0 = 128; K = 128; break;
        default: W = W2; ldw = 128; col0 = 0;  K = 256; break;
    }
    __nv_bfloat16* out = &g_wsp[tile][0];
    int idx = ob * 256 + threadIdx.x;
    int n = idx / K, k = idx - n * K;
    float w = W[(size_t)k * ldw + col0 + n];
    __nv_bfloat16 hi = __float2bfloat16(w);
    float r1 = __fsub_rn(w, __bfloat162float(hi));
    __nv_bfloat16 mid = __float2bfloat16(r1);
    float r2 = __fsub_rn(r1, __bfloat162float(mid));
    out[(size_t)(0 * 128 + n) * K + k] = hi;
    out[(size_t)(1 * 128 + n) * K + k] = mid;
    out[(size_t)(2 * 128 + n) * K + k] = __float2bfloat16(r2);
}

// =====================================================================
// x -> 3 bf16 splits, pure stream (layouts identical linear order)
// =====================================================================
__global__ void __launch_bounds__(256) k_xsplit(const float* __restrict__ x) {
    size_t i0 = ((size_t)blockIdx.x * 256 + threadIdx.x) * 8;
    const size_t step = (size_t)gridDim.x * 256 * 8;
    for (size_t i = i0; i < TOT; i += step) {
        float4 f0 = *reinterpret_cast<const float4*>(&x[i]);
        float4 f1 = *reinterpret_cast<const float4*>(&x[i + 4]);
        float a[8] = {f0.x, f0.y, f0.z, f0.w, f1.x, f1.y, f1.z, f1.w};
        uint32_t hp[4], mp[4], lp[4];
#pragma unroll
        for (int e = 0; e < 4; e++) {
            float v0 = a[2 * e], v1 = a[2 * e + 1];
            __nv_bfloat16 h0 = __float2bfloat16(v0), h1 = __float2bfloat16(v1);
            float r0 = __fsub_rn(v0, __bfloat162float(h0));
            float r1 = __fsub_rn(v1, __bfloat162float(h1));
            __nv_bfloat16 m0 = __float2bfloat16(r0), m1 = __float2bfloat16(r1);
            float s0 = __fsub_rn(r0, __bfloat162float(m0));
            float s1 = __fsub_rn(r1, __bfloat162float(m1));
            hp[e] = (uint32_t)*(uint16_t*)&h0 | ((uint32_t)*(uint16_t*)&h1 << 16);
            mp[e] = (uint32_t)*(uint16_t*)&m0 | ((uint32_t)*(uint16_t*)&m1 << 16);
            lp[e] = bf2x(s0, s1);
        }
        *reinterpret_cast<uint4*>(&g_xs[0][i]) = *reinterpret_cast<uint4*>(hp);
        *reinterpret_cast<uint4*>(&g_xs[1][i]) = *reinterpret_cast<uint4*>(mp);
        *reinterpret_cast<uint4*>(&g_xs[2][i]) = *reinterpret_cast<uint4*>(lp);
    }
}

// =====================================================================
// Memory mix + temporal lowpass; emits mlp splits (bf16)
// =====================================================================
__global__ void __launch_bounds__(128) k_mix(const float* __restrict__ x,
                                             const float* __restrict__ mx) {
    __shared__ float s_p[64 * 128];
    __shared__ ull  s_Mp[32 * 64];
    const int bn = blockIdx.x;
    const int b = bn >> 6, n = bn & 63;
    const int tid = threadIdx.x;

    for (int i = tid; i < 2048; i += 128) s_Mp[i] = g_Mp[i];

    const float* xb = x + (size_t)(b * N_ + n) * D_;
    const float* mb = mx + ((size_t)(n * B_ + b) * T_) * D_;
    for (int i = tid; i < 8192; i += 128) {
        float mv = mb[i];
        float mv2 = __fadd_rn(__fmul_rn(0.05f, mv), __fmul_rn(0.95f, mv));
        s_p[i] = __fmul_rn(xb[(size_t)(i >> 7) * BND + (i & 127)], mv2);
    }
    __syncthreads();

    const int d = tid;
    ull acc[32];
#pragma unroll
    for (int t2 = 0; t2 < 32; t2++) acc[t2] = 0ull;
    for (int s = 0; s < 64; s++) {
        ull cp = dup2(s_p[s * 128 + d]);
#pragma unroll
        for (int t2 = 0; t2 < 32; t2++) ffma2(acc[t2], s_Mp[t2 * 64 + s], cp);
    }
#pragma unroll
    for (int t2 = 0; t2 < 32; t2++) {
        float2 f = *reinterpret_cast<float2*>(&acc[t2]);
#pragma unroll
        for (int e = 0; e < 2; e++) {
            float v = (e == 0) ? f.x : f.y;
            size_t oi = ((size_t)(2 * t2 + e) * 4096 + bn) * 128 + d;
            __nv_bfloat16 hi = __float2bfloat16(v);
            float r1 = __fsub_rn(v, __bfloat162float(hi));
            __nv_bfloat16 mid = __float2bfloat16(r1);
            float r2 = __fsub_rn(r1, __bfloat162float(mid));
            g_ms[0][oi] = hi;
            g_ms[1][oi] = mid;
            g_ms[2][oi] = __float2bfloat16(r2);
        }
    }
}

// =====================================================================
// Double-buffered tensor-core GEMM + fused LIF. 1 CTA/SM, 2 x 96KB stages.
// Stage = khalf (64 k). NST = KCHUNKS*2 stages.
// =====================================================================
constexpr int STG = 98304;                  // 96KB per stage (3 A + 3 B tiles)
constexpr int SGEMM = 1024 + 2 * STG;       // 197632
constexpr int PPAD = 130;

template <int KCHUNKS, int MODE, int NSPLITS>
__global__ void __launch_bounds__(256, 1) k_mmag(
    const __nv_bfloat16* __restrict__ aspl, size_t asstride,
    const __nv_bfloat16* __restrict__ wsp,
    void* __restrict__ outp, int ldo, int ocol0,
    const float* __restrict__ gx,
    __nv_bfloat16* __restrict__ so0, __nv_bfloat16* __restrict__ so1,
    __nv_bfloat16* __restrict__ so2) {
    extern __shared__ __align__(16) char smem_raw[];
    const uint32_t sbase = smem_u32(smem_raw);
    float* s_pre = (float*)(smem_raw + 1024);
    const int bn0 = blockIdx.x * 2;
    const int tid = threadIdx.x;
    const int wid = tid >> 5, lane = tid & 31;
    constexpr int KTOT = KCHUNKS * 128;
    constexpr int NST = KCHUNKS * 2;

    const int m_base = (wid & 1) * 64;
    const int n_base = (wid >> 1) * 32;
    const int sub = lane >> 3, lr = lane & 7;
    const int arow_off = (sub & 1) * 8 + lr;
    const int akc = (sub >> 1) * 8;
    const int brow_off = (sub >> 1) * 8 + lr;
    const int bkc = (sub & 1) * 8;

    auto load_stage = [&](int s) {
        const int ch = s >> 1, kh = s & 1;
        const uint32_t dst = sbase + 1024 + (s & 1) * STG;
        // A splits
        for (int u = tid; u < NSPLITS * 1024; u += 256) {
            int sp = u >> 10, r = u & 1023, m = r >> 3, g = r & 7;
            int t = m & 63, tile = m >> 6;
            const __nv_bfloat16* src = aspl + (size_t)sp * asstride +
                ((size_t)t * 4096 + bn0 + tile) * KTOT + ch * 128 + kh * 64 + g * 8;
            cpa16(dst + sp * 16384 + sw128((m << 7) + (g << 4)), src);
        }
        // B splits
        for (int u = tid; u < 3072; u += 256) {
            int sp = u >> 10, r = u & 1023, n = r >> 3, g = r & 7;
            const __nv_bfloat16* src =
                wsp + ((size_t)(sp * 128 + n) * KTOT + ch * 128 + kh * 64 + g * 8);
            cpa16(dst + 49152 + sp * 16384 + sw128((n << 7) + (g << 4)), src);
        }
        cpa_commit();
    };

    float acc[4][4][4];
#pragma unroll
    for (int i = 0; i < 4; i++)
#pragma unroll
        for (int j = 0; j < 4; j++)
#pragma unroll
            for (int e = 0; e < 4; e++) acc[i][j][e] = 0.f;

    load_stage(0);
    if (NST > 1) load_stage(1);

#pragma unroll
    for (int s = 0; s < NST; s++) {
        if (s + 1 < NST) cpa_wait<1>(); else cpa_wait<0>();
        __syncthreads();

        const uint32_t Abuf = sbase + 1024 + (s & 1) * STG;
        const uint32_t Bbuf = Abuf + 49152;
        const int NP = (NSPLITS == 3) ? 6 : (NSPLITS == 2 ? 5 : 3);
        const int PAs[6] = {0, 0, 1, 0, 1, 2};
        const int PBs[6] = {0, 1, 0, 2, 1, 0};
        const int PB1[6] = {0, 1, 2, 0, 0, 0};

        for (int p = 0; p < NP; p++) {
            int As = (NSPLITS == 1) ? 0 : PAs[p];
            int Bs = (NSPLITS == 1) ? PB1[p] : PBs[p];
            uint32_t Abase = Abuf + As * 16384;
            uint32_t Bbase = Bbuf + Bs * 16384;
#pragma unroll
            for (int ks = 0; ks < 4; ks++) {
                int k0 = ks * 16;
                uint32_t afr[4][4];
#pragma unroll
                for (int mf = 0; mf < 4; mf++)
                    ldsm4(afr[mf], Abase +
                          sw128(((m_base + mf * 16 + arow_off) << 7) + (k0 + akc) * 2));
                uint32_t bfr[2][4];
#pragma unroll
                for (int nf2 = 0; nf2 < 2; nf2++)
                    ldsm4(bfr[nf2], Bbase +
                          sw128(((n_base + nf2 * 16 + brow_off) << 7) + (k0 + bkc) * 2));
#pragma unroll
                for (int mf = 0; mf < 4; mf++)
#pragma unroll
                    for (int nf = 0; nf < 4; nf++)
                        mma16816(acc[mf][nf], afr[mf],
                                 bfr[nf >> 1][(nf & 1) * 2], bfr[nf >> 1][(nf & 1) * 2 + 1]);
            }
        }
        __syncthreads();             // all warps done reading buf (s&1)
        if (s + 2 < NST) load_stage(s + 2);
    }

    // ---- store fragments to s_pre ----
    {
        const int qr = lane >> 2, qc = (lane & 3) * 2;
#pragma unroll
        for (int mf = 0; mf < 4; mf++)
#pragma unroll
            for (int nf = 0; nf < 4; nf++) {
                int row = m_base + mf * 16 + qr;
                int col = n_base + nf * 8 + qc;
                *reinterpret_cast<float2*>(&s_pre[row * PPAD + col]) =
                    make_float2(acc[mf][nf][0], acc[mf][nf][1]);
                *reinterpret_cast<float2*>(&s_pre[(row + 8) * PPAD + col]) =
                    make_float2(acc[mf][nf][2], acc[mf][nf][3]);
            }
    }
    __syncthreads();

    // ---- fused LIF scan ----
    {
        const int tile = tid >> 7, c = tid & 127;
        const int bn = bn0 + tile;
        float vmem = 0.f;
        const size_t ostride = (size_t)4096 * ldo;
        const size_t obase = (size_t)bn * ldo + ocol0 + c;
        const size_t gbase = (size_t)bn * 128 + c;
#pragma unroll 1
        for (int t = 0; t < 64; t++) {
            float p = s_pre[(tile * 64 + t) * PPAD + c];
            vmem = __fadd_rn(vmem, __fmul_rn(__fsub_rn(p, vmem), 0.5f));
            float spk = (vmem >= 1.0f) ? 1.0f : 0.0f;
            if (vmem >= 1.0f) vmem = 0.0f;
            size_t oi = obase + (size_t)t * ostride;
            if (MODE == 0) {
                ((__nv_bfloat16*)outp)[oi] = __float2bfloat16(spk);
            } else {
                float g = gx[gbase + (size_t)t * (size_t)BND];
                float val = __fmul_rn(g, __fsub_rn(1.0f, spk));
                ((float*)outp)[oi] = val;
                if (MODE == 1) {
                    __nv_bfloat16 hi = __float2bfloat16(val);
                    float r1 = __fsub_rn(val, __bfloat162float(hi));
                    __nv_bfloat16 mid = __float2bfloat16(r1);
                    float r2 = __fsub_rn(r1, __bfloat162float(mid));
                    so0[oi] = hi;
                    so1[oi] = mid;
                    so2[oi] = __float2bfloat16(r2);
                }
            }
        }
    }
}

// =====================================================================
// Attention via tensor cores (exact bf16 in/out), emits o splits.
// =====================================================================
constexpr int ATT_Q = 0, ATT_K = 16384, ATT_V = 32768, ATT_AT = 49152;
constexpr int SATT = 65536;

__global__ void __launch_bounds__(256) k_attn3(const __nv_bfloat16* __restrict__ q,
                                               const __nv_bfloat16* __restrict__ k,
                                               const __nv_bfloat16* __restrict__ v,
                                               __nv_bfloat16* __restrict__ so0,
                                               __nv_bfloat16* __restrict__ so1) {
    extern __shared__ __align__(16) char sm_raw[];
    const uint32_t sbase = smem_u32(sm_raw);
    const size_t base = (size_t)blockIdx.x * 8192;
    const int tid = threadIdx.x;
    const int wid = tid >> 5, lane = tid & 31;

    for (int u = tid; u < 4096; u += 256) {
        int n = u >> 6;
        int d = (u & 63) * 2;
        int h = d >> 6, dd = d & 63;
        uint32_t qp = *reinterpret_cast<const uint32_t*>(&q[base + 2 * u]);
        uint32_t kp = *reinterpret_cast<const uint32_t*>(&k[base + 2 * u]);
        uint32_t vp = *reinterpret_cast<const uint32_t*>(&v[base + 2 * u]);
        uint32_t off = sw128((n << 7) + (dd << 1));
        *reinterpret_cast<uint32_t*>(sm_raw + ATT_Q + h * 8192 + off) = qp;
        *reinterpret_cast<uint32_t*>(sm_raw + ATT_K + h * 8192 + off) = kp;
        *reinterpret_cast<uint16_t*>(sm_raw + ATT_V + h * 8192 +
            sw128((dd << 7) + (n << 1))) = (uint16_t)(vp & 0xffffu);
        *reinterpret_cast<uint16_t*>(sm_raw + ATT_V + h * 8192 +
            sw128(((dd + 1) << 7) + (n << 1))) = (uint16_t)(vp >> 16);
    }
    __syncthreads();

    const int sub = lane >> 3, lr = lane & 7;
    const int arow_off = (sub & 1) * 8 + lr;
    const int akc = (sub >> 1) * 8;
    const int brow_off = (sub >> 1) * 8 + lr;
    const int bkc = (sub & 1) * 8;
    const int qr = lane >> 2, qc = (lane & 3) * 2;

    float acc[8][4];

    {
        const int h = wid & 1;
        const int n_b = (wid >> 1) * 16;
        uint32_t Abase = sbase + ATT_Q + h * 8192;
        uint32_t Bbase = sbase + ATT_K + h * 8192;
#pragma unroll
        for (int j = 0; j < 8; j++)
#pragma unroll
            for (int e = 0; e < 4; e++) acc[j][e] = 0.f;
#pragma unroll
        for (int ks = 0; ks < 4; ks++) {
            int k0 = ks * 16;
            uint32_t afr[4];
            ldsm4(afr, Abase + sw128(((n_b + arow_off) << 7) + (k0 + akc) * 2));
#pragma unroll
            for (int mf2 = 0; mf2 < 4; mf2++) {
                uint32_t bfr[4];
                ldsm4(bfr, Bbase + sw128(((mf2 * 16 + brow_off) << 7) + (k0 + bkc) * 2));
                mma16816(acc[mf2 * 2 + 0], afr, bfr[0], bfr[1]);
                mma16816(acc[mf2 * 2 + 1], afr, bfr[2], bfr[3]);
            }
        }
        uint32_t Obase = (uint32_t)(ATT_AT + h * 8192);
#pragma unroll
        for (int j = 0; j < 8; j++) {
            int m_col = j * 8 + qc;
            int r0 = n_b + qr;
            *reinterpret_cast<uint32_t*>(sm_raw + Obase +
                sw128((r0 << 7) + m_col * 2)) = bf2x(acc[j][0] * 0.125f, acc[j][1] * 0.125f);
            *reinterpret_cast<uint32_t*>(sm_raw + Obase +
                sw128(((r0 + 8) << 7) + m_col * 2)) = bf2x(acc[j][2] * 0.125f, acc[j][3] * 0.125f);
        }
    }
    __syncthreads();

    {
        const int h = wid >> 2;
        const int n_b = (wid & 3) * 16;
        uint32_t Abase = sbase + ATT_AT + h * 8192;
        uint32_t Bbase = sbase + ATT_V + h * 8192;
#pragma unroll
        for (int j = 0; j < 8; j++)
#pragma unroll
            for (int e = 0; e < 4; e++) acc[j][e] = 0.f;
#pragma unroll
        for (int ks = 0; ks < 4; ks++) {
            int k0 = ks * 16;
            uint32_t afr[4];
            ldsm4(afr, Abase + sw128(((n_b + arow_off) << 7) + (k0 + akc) * 2));
#pragma unroll
            for (int df = 0; df < 4; df++) {
                uint32_t bfr[4];
                ldsm4(bfr, Bbase + sw128(((df * 16 + brow_off) << 7) + (k0 + bkc) * 2));
                mma16816(acc[df * 2 + 0], afr, bfr[0], bfr[1]);
                mma16816(acc[df * 2 + 1], afr, bfr[2], bfr[3]);
            }
        }
#pragma unroll
        for (int j = 0; j < 8; j++) {
            int d_col = h * 64 + j * 8 + qc;
#pragma unroll
            for (int half = 0; half < 2; half++) {
                int r0 = n_b + qr + half * 8;
                float f0 = acc[j][half * 2 + 0], f1 = acc[j][half * 2 + 1];
                float h0 = __bfloat162float(__float2bfloat16(f0));
                float h1v = __bfloat162float(__float2bfloat16(f1));
                size_t oi = base + (size_t)r0 * 128 + d_col;
                *reinterpret_cast<uint32_t*>(&so0[oi]) = bf2x(f0, f1);
                *reinterpret_cast<uint32_t*>(&so1[oi]) =
                    bf2x(__fsub_rn(f0, h0), __fsub_rn(f1, h1v));
            }
        }
    }
}

// =====================================================================
// Host side
// =====================================================================
extern "C" void kernel_launch(void* const* d_in, const int* in_sizes, int n_in,
                              void* d_out, int out_size) {
    const float* x  = (const float*)d_in[0];
    const float* mx = (const float*)d_in[1];
    const float* Wq = (const float*)d_in[2];
    const float* Wk = (const float*)d_in[3];
    const float* Wv = (const float*)d_in[4];
    const float* Wo = (const float*)d_in[5];
    const float* W1 = (const float*)d_in[6];
    const float* W2 = (const float*)d_in[7];
    float* out = (float*)d_out;

    void *p_xs, *p_ms, *p_os, *p_xgs, *p_xg, *p_q, *p_k, *p_v, *p_h1, *p_wsp;
    cudaGetSymbolAddress(&p_xs, g_xs);
    cudaGetSymbolAddress(&p_ms, g_ms);
    cudaGetSymbolAddress(&p_os, g_os);
    cudaGetSymbolAddress(&p_xgs, g_xgs);
    cudaGetSymbolAddress(&p_xg, g_xg);
    cudaGetSymbolAddress(&p_q, g_q);
    cudaGetSymbolAddress(&p_k, g_k);
    cudaGetSymbolAddress(&p_v, g_v);
    cudaGetSymbolAddress(&p_h1, g_h1);
    cudaGetSymbolAddress(&p_wsp, g_wsp);
    __nv_bfloat16* xs = (__nv_bfloat16*)p_xs;
    __nv_bfloat16* ms = (__nv_bfloat16*)p_ms;
    __nv_bfloat16* os = (__nv_bfloat16*)p_os;
    __nv_bfloat16* xgs = (__nv_bfloat16*)p_xgs;
    __nv_bfloat16* wsp = (__nv_bfloat16*)p_wsp;
    const size_t WSTRIDE = 3 * 128 * 256;

    cudaFuncSetAttribute(k_mmag<1, 0, 3>, cudaFuncAttributeMaxDynamicSharedMemorySize, SGEMM);
    cudaFuncSetAttribute(k_mmag<1, 1, 2>, cudaFuncAttributeMaxDynamicSharedMemorySize, SGEMM);
    cudaFuncSetAttribute(k_mmag<2, 2, 1>, cudaFuncAttributeMaxDynamicSharedMemorySize, SGEMM);
    cudaFuncSetAttribute(k_attn3, cudaFuncAttributeMaxDynamicSharedMemorySize, SATT);

    k_dct<<<64, 64>>>();                                                    // 1
    k_pack<<<32, 64>>>();                                                   // 2
    k_wsplit_all<<<512, 256>>>(Wq, Wk, Wv, Wo, W1, W2);                     // 3
    k_xsplit<<<2048, 256>>>(x);                                             // 4
    k_mix<<<4096, 128>>>(x, mx);                                            // 5
    // q = LIF(x @ Wq)
    k_mmag<1, 0, 3><<<2048, 256, SGEMM>>>(xs, TOT, wsp + 0 * WSTRIDE,
        p_q, 128, 0, nullptr, nullptr, nullptr, nullptr);                   // 6 <- profiled
    k_mmag<1, 0, 3><<<2048, 256, SGEMM>>>(ms, TOT, wsp + 1 * WSTRIDE,
        p_k, 128, 0, nullptr, nullptr, nullptr, nullptr);                   // 7
    k_mmag<1, 0, 3><<<2048, 256, SGEMM>>>(ms, TOT, wsp + 2 * WSTRIDE,
        p_v, 128, 0, nullptr, nullptr, nullptr, nullptr);                   // 8
    k_attn3<<<4096, 256, SATT>>>((const __nv_bfloat16*)p_q, (const __nv_bfloat16*)p_k,
        (const __nv_bfloat16*)p_v, os, os + TOT);                           // 9
    k_mmag<1, 1, 2><<<2048, 256, SGEMM>>>(os, TOT, wsp + 3 * WSTRIDE,
        p_xg, 128, 0, x, xgs, xgs + TOT, xgs + 2 * TOT);                    // 10
    k_mmag<1, 0, 3><<<2048, 256, SGEMM>>>(xgs, TOT, wsp + 4 * WSTRIDE,
        p_h1, 256, 0, nullptr, nullptr, nullptr, nullptr);                  // 11
    k_mmag<1, 0, 3><<<2048, 256, SGEMM>>>(xgs, TOT, wsp + 5 * WSTRIDE,
        p_h1, 256, 128, nullptr, nullptr, nullptr, nullptr);                // 12
    k_mmag<2, 2, 1><<<2048, 256, SGEMM>>>((const __nv_bfloat16*)p_h1, 0,
        wsp + 6 * WSTRIDE, out, 128, 0, (const float*)p_xg,
        nullptr, nullptr, nullptr);                                         // 13
}